// round 5
// baseline (speedup 1.0000x reference)
#include <cuda_runtime.h>

#define NTHREADS 256
#define NWARPS   8
#define R        16            // rows per warp
#define ROWS_CTA (NWARPS * R)  // 128
#define DIM_NX 64
#define DIM_NQ 64
#define DIM_NU 16

// smem floats:
//  sCA  64*32*4  = 8192   {C1[l][j], C1[l+32][j], A[l][j], A[l+32][j]}
//  sDB  64*32*4  = 8192   {D11[l][j],D11[l+32][j],B1[l][j],B1[l+32][j]}
//  sDU  16*32*4  = 2048   {D12[l][k],D12[l+32][k],B2[l][k],B2[l+32][k]}
//  xs2  128*64*2 = 16384  duplicated pairs (x_j, x_j)
//  us2  128*16*2 = 4096   duplicated pairs (u_k, u_k)
#define SMEM_FLOATS (8192*2 + 2048 + ROWS_CTA*DIM_NX*2 + ROWS_CTA*DIM_NU*2)

typedef unsigned long long u64t;

__device__ __forceinline__ u64t pk2(float a, float b) {
    u64t r; asm("mov.b64 %0, {%1, %2};" : "=l"(r) : "f"(a), "f"(b)); return r;
}
__device__ __forceinline__ void up2(u64t v, float& a, float& b) {
    asm("mov.b64 {%0, %1}, %2;" : "=f"(a), "=f"(b) : "l"(v));
}
__device__ __forceinline__ u64t fma2(u64t a, u64t b, u64t c) {
    u64t d; asm("fma.rn.f32x2 %0, %1, %2, %3;" : "=l"(d) : "l"(a), "l"(b), "l"(c));
    return d;
}

struct uu2 { u64t x, y; };   // maps onto one LDS.128

__global__ void __launch_bounds__(NTHREADS)
renl2_kernel(const float* __restrict__ gx,  const float* __restrict__ gu,
             const float* __restrict__ gA,  const float* __restrict__ gB1,
             const float* __restrict__ gB2, const float* __restrict__ gC1,
             const float* __restrict__ gD11,const float* __restrict__ gD12,
             const float* __restrict__ gbv, const float* __restrict__ gbx,
             float* __restrict__ gout, int N)
{
    extern __shared__ float sm[];
    float* sCA = sm;                        // 8192 floats
    float* sDB = sCA + 8192;                // 8192
    float* sDU = sDB + 8192;                // 2048
    float* xs2 = sDU + 2048;                // 16384 (float2-dup x)
    float* us2 = xs2 + ROWS_CTA*DIM_NX*2;   // 4096  (float2-dup u)

    const int tid     = threadIdx.x;
    const int lane    = tid & 31;
    const int wid     = tid >> 5;
    const int rowbase = blockIdx.x * ROWS_CTA;

    // ---- stage interleaved matrices (one-time per CTA)
    float4* sCA4 = reinterpret_cast<float4*>(sCA);
    float4* sDB4 = reinterpret_cast<float4*>(sDB);
    float4* sDU4 = reinterpret_cast<float4*>(sDU);
    #pragma unroll 1
    for (int idx = tid; idx < 2048; idx += NTHREADS) {
        const int j = idx >> 5, l = idx & 31;
        sCA4[idx] = make_float4(gC1 [l*64+j], gC1 [(l+32)*64+j],
                                gA  [l*64+j], gA  [(l+32)*64+j]);
        sDB4[idx] = make_float4(gD11[l*64+j], gD11[(l+32)*64+j],
                                gB1 [l*64+j], gB1 [(l+32)*64+j]);
    }
    #pragma unroll 1
    for (int idx = tid; idx < 512; idx += NTHREADS) {
        const int k = idx >> 5, l = idx & 31;
        sDU4[idx] = make_float4(gD12[l*16+k], gD12[(l+32)*16+k],
                                gB2 [l*16+k], gB2 [(l+32)*16+k]);
    }

    // ---- stage x, u as duplicated float2 pairs (coalesced float4 reads)
    const float4* gx4 = reinterpret_cast<const float4*>(gx + (size_t)rowbase * DIM_NX);
    float2* xs2v = reinterpret_cast<float2*>(xs2);
    #pragma unroll 1
    for (int i = tid; i < ROWS_CTA * DIM_NX / 4; i += NTHREADS) {
        const int row = i >> 4;
        if (rowbase + row < N) {
            const float4 v = gx4[i];
            float2* dst = xs2v + row * DIM_NX + (i & 15) * 4;
            dst[0] = make_float2(v.x, v.x);
            dst[1] = make_float2(v.y, v.y);
            dst[2] = make_float2(v.z, v.z);
            dst[3] = make_float2(v.w, v.w);
        }
    }
    const float4* gu4 = reinterpret_cast<const float4*>(gu + (size_t)rowbase * DIM_NU);
    float2* us2v = reinterpret_cast<float2*>(us2);
    #pragma unroll 1
    for (int i = tid; i < ROWS_CTA * DIM_NU / 4; i += NTHREADS) {
        const int row = i >> 2;
        if (rowbase + row < N) {
            const float4 v = gu4[i];
            float2* dst = us2v + row * DIM_NU + (i & 3) * 4;
            dst[0] = make_float2(v.x, v.x);
            dst[1] = make_float2(v.y, v.y);
            dst[2] = make_float2(v.z, v.z);
            dst[3] = make_float2(v.w, v.w);
        }
    }
    __syncthreads();

    const uu2* uCA = reinterpret_cast<const uu2*>(sCA);
    const uu2* uDB = reinterpret_cast<const uu2*>(sDB);
    const uu2* uDU = reinterpret_cast<const uu2*>(sDU);
    const uu2* uXS = reinterpret_cast<const uu2*>(xs2) + (size_t)(wid * R) * (DIM_NX/2);
    const uu2* uUS = reinterpret_cast<const uu2*>(us2) + (size_t)(wid * R) * (DIM_NU/2);

    // accumulators: lane l holds (v[l], v[l+32]) packed, per row
    const u64t bv2 = pk2(gbv[lane], gbv[lane + 32]);
    const u64t bx2 = pk2(gbx[lane], gbx[lane + 32]);
    u64t wac[R], opk[R];
    #pragma unroll
    for (int r = 0; r < R; r++) { wac[r] = bv2; opk[r] = bx2; }

    // ===== phase A: w += C1 x ; out += A x   (two j per iteration)
    #pragma unroll 2
    for (int jp = 0; jp < DIM_NX/2; jp++) {
        const uu2 m0 = uCA[(2*jp+0)*32 + lane];   // {C1, A} for j=2jp
        const uu2 m1 = uCA[(2*jp+1)*32 + lane];   // {C1, A} for j=2jp+1
        #pragma unroll
        for (int r = 0; r < R; r++) {
            const uu2 xx = uXS[r * (DIM_NX/2) + jp];  // broadcast {(xj,xj),(xj1,xj1)}
            wac[r] = fma2(m0.x, xx.x, wac[r]);
            opk[r] = fma2(m0.y, xx.x, opk[r]);
            wac[r] = fma2(m1.x, xx.y, wac[r]);
            opk[r] = fma2(m1.y, xx.y, opk[r]);
        }
    }
    // ===== phase A-u: w += D12 u ; out += B2 u
    #pragma unroll 2
    for (int kp = 0; kp < DIM_NU/2; kp++) {
        const uu2 m0 = uDU[(2*kp+0)*32 + lane];
        const uu2 m1 = uDU[(2*kp+1)*32 + lane];
        #pragma unroll
        for (int r = 0; r < R; r++) {
            const uu2 uu = uUS[r * (DIM_NU/2) + kp];
            wac[r] = fma2(m0.x, uu.x, wac[r]);
            opk[r] = fma2(m0.y, uu.x, opk[r]);
            wac[r] = fma2(m1.x, uu.y, wac[r]);
            opk[r] = fma2(m1.y, uu.y, opk[r]);
        }
    }

    // ===== fused substitution + B1 epilogue
    //   step j: w_j = relu(wac lane j), wac += D11[:,j] w_j, out += B1[:,j] w_j
    //   D11 strictly lower triangular -> lanes with row index <= j add exactly 0.
    #pragma unroll 2
    for (int j = 0; j < 32; j++) {                       // w indices 0..31 (lo)
        const uu2 db = uDB[j*32 + lane];                 // {D11, B1} column j
        #pragma unroll
        for (int r = 0; r < R; r++) {
            float alo, ahi; up2(wac[r], alo, ahi);
            const float wj = fmaxf(__shfl_sync(0xffffffffu, alo, j), 0.0f);
            const u64t w2 = pk2(wj, wj);
            wac[r] = fma2(db.x, w2, wac[r]);
            opk[r] = fma2(db.y, w2, opk[r]);
        }
    }
    #pragma unroll 2
    for (int j = 32; j < 64; j++) {                      // w indices 32..63 (hi)
        const uu2 db = uDB[j*32 + lane];
        #pragma unroll
        for (int r = 0; r < R; r++) {
            float alo, ahi; up2(wac[r], alo, ahi);
            const float wj = fmaxf(__shfl_sync(0xffffffffu, ahi, j - 32), 0.0f);
            const u64t w2 = pk2(wj, wj);
            wac[r] = fma2(db.x, w2, wac[r]);
            opk[r] = fma2(db.y, w2, opk[r]);
        }
    }

    // ===== store: lane l writes cols l and l+32 (two coalesced 128B halves)
    #pragma unroll
    for (int r = 0; r < R; r++) {
        const int row = rowbase + wid * R + r;
        if (row < N) {
            float olo, ohi; up2(opk[r], olo, ohi);
            gout[(size_t)row * DIM_NX + lane]      = olo;
            gout[(size_t)row * DIM_NX + lane + 32] = ohi;
        }
    }
}

extern "C" void kernel_launch(void* const* d_in, const int* in_sizes, int n_in,
                              void* d_out, int out_size) {
    (void)n_in; (void)out_size;
    const float* x   = (const float*)d_in[0];
    const float* u   = (const float*)d_in[1];
    const float* A   = (const float*)d_in[2];
    const float* B1  = (const float*)d_in[3];
    const float* B2  = (const float*)d_in[4];
    const float* C1  = (const float*)d_in[5];
    const float* D11 = (const float*)d_in[6];
    const float* D12 = (const float*)d_in[7];
    const float* bv  = (const float*)d_in[8];
    const float* bx  = (const float*)d_in[9];
    float* out = (float*)d_out;

    const int N = in_sizes[0] / DIM_NX;                 // 262144
    const int grid = (N + ROWS_CTA - 1) / ROWS_CTA;     // 2048
    const size_t smem_bytes = (size_t)SMEM_FLOATS * sizeof(float);  // 152 KB

    cudaFuncSetAttribute(renl2_kernel,
                         cudaFuncAttributeMaxDynamicSharedMemorySize,
                         (int)smem_bytes);

    renl2_kernel<<<grid, NTHREADS, smem_bytes>>>(
        x, u, A, B1, B2, C1, D11, D12, bv, bx, out, N);
}

// round 6
// speedup vs baseline: 1.3225x; 1.3225x over previous
#include <cuda_runtime.h>

#define NTHREADS 256
#define NWARPS   8
#define R        16            // rows per warp
#define ROWS_CTA (NWARPS * R)  // 128
#define DIM_NX 64
#define DIM_NQ 64
#define DIM_NU 16

// smem floats:
//  sCA  64*32*4  = 8192   {C1[l][j], C1[l+32][j], A[l][j],  A[l+32][j]}
//  sDB  64*32*4  = 8192   {D11[l][j],D11[l+32][j],B1[l][j], B1[l+32][j]}
//  sDU  16*32*4  = 2048   {D12[l][k],D12[l+32][k],B2[l][k], B2[l+32][k]}
//  xs   128*64   = 8192
//  us   128*16   = 2048
//  total 28672 floats = 112 KB  -> 2 CTAs/SM
#define SMEM_FLOATS (8192*2 + 2048 + ROWS_CTA*DIM_NX + ROWS_CTA*DIM_NU)

typedef unsigned long long u64t;

__device__ __forceinline__ u64t pk2(float a, float b) {
    u64t r; asm("mov.b64 %0, {%1, %2};" : "=l"(r) : "f"(a), "f"(b)); return r;
}
__device__ __forceinline__ void up2(u64t v, float& a, float& b) {
    asm("mov.b64 {%0, %1}, %2;" : "=f"(a), "=f"(b) : "l"(v));
}
__device__ __forceinline__ u64t fma2(u64t a, u64t b, u64t c) {
    u64t d; asm("fma.rn.f32x2 %0, %1, %2, %3;" : "=l"(d) : "l"(a), "l"(b), "l"(c));
    return d;
}

struct uu2 { u64t x, y; };   // one LDS.128: {pair0, pair1}

__global__ void __launch_bounds__(NTHREADS)
renl2_kernel(const float* __restrict__ gx,  const float* __restrict__ gu,
             const float* __restrict__ gA,  const float* __restrict__ gB1,
             const float* __restrict__ gB2, const float* __restrict__ gC1,
             const float* __restrict__ gD11,const float* __restrict__ gD12,
             const float* __restrict__ gbv, const float* __restrict__ gbx,
             float* __restrict__ gout, int N)
{
    extern __shared__ float sm[];
    float* sCA = sm;                        // 8192 floats
    float* sDB = sCA + 8192;                // 8192
    float* sDU = sDB + 8192;                // 2048
    float* xs  = sDU + 2048;                // 8192
    float* us  = xs + ROWS_CTA*DIM_NX;      // 2048

    const int tid     = threadIdx.x;
    const int lane    = tid & 31;
    const int wid     = tid >> 5;
    const int rowbase = blockIdx.x * ROWS_CTA;

    // ---- stage interleaved matrices (one-time per CTA)
    float4* sCA4 = reinterpret_cast<float4*>(sCA);
    float4* sDB4 = reinterpret_cast<float4*>(sDB);
    float4* sDU4 = reinterpret_cast<float4*>(sDU);
    #pragma unroll 1
    for (int idx = tid; idx < 2048; idx += NTHREADS) {
        const int j = idx >> 5, l = idx & 31;
        sCA4[idx] = make_float4(gC1 [l*64+j], gC1 [(l+32)*64+j],
                                gA  [l*64+j], gA  [(l+32)*64+j]);
        sDB4[idx] = make_float4(gD11[l*64+j], gD11[(l+32)*64+j],
                                gB1 [l*64+j], gB1 [(l+32)*64+j]);
    }
    #pragma unroll 1
    for (int idx = tid; idx < 512; idx += NTHREADS) {
        const int k = idx >> 5, l = idx & 31;
        sDU4[idx] = make_float4(gD12[l*16+k], gD12[(l+32)*16+k],
                                gB2 [l*16+k], gB2 [(l+32)*16+k]);
    }

    // ---- stage x, u tiles: contiguous copy (fully coalesced float4)
    const float4* gx4 = reinterpret_cast<const float4*>(gx + (size_t)rowbase * DIM_NX);
    float4* xs4 = reinterpret_cast<float4*>(xs);
    #pragma unroll 1
    for (int i = tid; i < ROWS_CTA * DIM_NX / 4; i += NTHREADS) {
        if (rowbase + (i >> 4) < N) xs4[i] = gx4[i];
    }
    const float4* gu4 = reinterpret_cast<const float4*>(gu + (size_t)rowbase * DIM_NU);
    float4* us4 = reinterpret_cast<float4*>(us);
    #pragma unroll 1
    for (int i = tid; i < ROWS_CTA * DIM_NU / 4; i += NTHREADS) {
        if (rowbase + (i >> 2) < N) us4[i] = gu4[i];
    }
    __syncthreads();

    const uu2* uCA = reinterpret_cast<const uu2*>(sCA);
    const uu2* uDB = reinterpret_cast<const uu2*>(sDB);
    const uu2* uDU = reinterpret_cast<const uu2*>(sDU);
    const float4* myxs4 = reinterpret_cast<const float4*>(xs + (size_t)(wid*R)*DIM_NX);
    const float4* myus4 = reinterpret_cast<const float4*>(us + (size_t)(wid*R)*DIM_NU);

    // accumulators: lane l holds (v[l], v[l+32]) packed, per row
    const u64t bv2 = pk2(gbv[lane], gbv[lane + 32]);
    const u64t bx2 = pk2(gbx[lane], gbx[lane + 32]);
    u64t wac[R], opk[R];
    #pragma unroll
    for (int r = 0; r < R; r++) { wac[r] = bv2; opk[r] = bx2; }

    // ===== phase A: w += C1 x ; out += A x   (4 j per x-load)
    #pragma unroll 1
    for (int jb = 0; jb < DIM_NX/4; jb++) {
        const uu2 m0 = uCA[(4*jb+0)*32 + lane];   // {C1pair, Apair} j=4jb
        const uu2 m1 = uCA[(4*jb+1)*32 + lane];
        const uu2 m2 = uCA[(4*jb+2)*32 + lane];
        const uu2 m3 = uCA[(4*jb+3)*32 + lane];
        #pragma unroll
        for (int r = 0; r < R; r++) {
            const float4 xv = myxs4[r * (DIM_NX/4) + jb];  // broadcast LDS.128
            const u64t x0 = pk2(xv.x, xv.x);
            const u64t x1 = pk2(xv.y, xv.y);
            const u64t x2 = pk2(xv.z, xv.z);
            const u64t x3 = pk2(xv.w, xv.w);
            wac[r] = fma2(m0.x, x0, wac[r]);  opk[r] = fma2(m0.y, x0, opk[r]);
            wac[r] = fma2(m1.x, x1, wac[r]);  opk[r] = fma2(m1.y, x1, opk[r]);
            wac[r] = fma2(m2.x, x2, wac[r]);  opk[r] = fma2(m2.y, x2, opk[r]);
            wac[r] = fma2(m3.x, x3, wac[r]);  opk[r] = fma2(m3.y, x3, opk[r]);
        }
    }
    // ===== phase A-u: w += D12 u ; out += B2 u   (4 k per u-load)
    #pragma unroll 1
    for (int kb = 0; kb < DIM_NU/4; kb++) {
        const uu2 m0 = uDU[(4*kb+0)*32 + lane];
        const uu2 m1 = uDU[(4*kb+1)*32 + lane];
        const uu2 m2 = uDU[(4*kb+2)*32 + lane];
        const uu2 m3 = uDU[(4*kb+3)*32 + lane];
        #pragma unroll
        for (int r = 0; r < R; r++) {
            const float4 uv = myus4[r * (DIM_NU/4) + kb];  // broadcast LDS.128
            const u64t u0 = pk2(uv.x, uv.x);
            const u64t u1 = pk2(uv.y, uv.y);
            const u64t u2 = pk2(uv.z, uv.z);
            const u64t u3 = pk2(uv.w, uv.w);
            wac[r] = fma2(m0.x, u0, wac[r]);  opk[r] = fma2(m0.y, u0, opk[r]);
            wac[r] = fma2(m1.x, u1, wac[r]);  opk[r] = fma2(m1.y, u1, opk[r]);
            wac[r] = fma2(m2.x, u2, wac[r]);  opk[r] = fma2(m2.y, u2, opk[r]);
            wac[r] = fma2(m3.x, u3, wac[r]);  opk[r] = fma2(m3.y, u3, opk[r]);
        }
    }

    // ===== fused substitution + B1 epilogue
    //   step j: w_j = relu(wac lane j); wac += D11[:,j] w_j; out += B1[:,j] w_j
    //   D11 strictly lower triangular -> lanes with row index <= j add exactly 0.
    #pragma unroll 2
    for (int j = 0; j < 32; j++) {                       // w indices 0..31 (lo)
        const uu2 db = uDB[j*32 + lane];                 // {D11pair, B1pair} col j
        #pragma unroll
        for (int r = 0; r < R; r++) {
            float alo, ahi; up2(wac[r], alo, ahi);
            const float wj = fmaxf(__shfl_sync(0xffffffffu, alo, j), 0.0f);
            const u64t w2 = pk2(wj, wj);
            wac[r] = fma2(db.x, w2, wac[r]);
            opk[r] = fma2(db.y, w2, opk[r]);
        }
    }
    #pragma unroll 2
    for (int j = 32; j < 64; j++) {                      // w indices 32..63 (hi)
        const uu2 db = uDB[j*32 + lane];
        #pragma unroll
        for (int r = 0; r < R; r++) {
            float alo, ahi; up2(wac[r], alo, ahi);
            const float wj = fmaxf(__shfl_sync(0xffffffffu, ahi, j - 32), 0.0f);
            const u64t w2 = pk2(wj, wj);
            wac[r] = fma2(db.x, w2, wac[r]);
            opk[r] = fma2(db.y, w2, opk[r]);
        }
    }

    // ===== store: lane l writes cols l and l+32 (two coalesced 128B halves)
    #pragma unroll
    for (int r = 0; r < R; r++) {
        const int row = rowbase + wid * R + r;
        if (row < N) {
            float olo, ohi; up2(opk[r], olo, ohi);
            gout[(size_t)row * DIM_NX + lane]      = olo;
            gout[(size_t)row * DIM_NX + lane + 32] = ohi;
        }
    }
}

extern "C" void kernel_launch(void* const* d_in, const int* in_sizes, int n_in,
                              void* d_out, int out_size) {
    (void)n_in; (void)out_size;
    const float* x   = (const float*)d_in[0];
    const float* u   = (const float*)d_in[1];
    const float* A   = (const float*)d_in[2];
    const float* B1  = (const float*)d_in[3];
    const float* B2  = (const float*)d_in[4];
    const float* C1  = (const float*)d_in[5];
    const float* D11 = (const float*)d_in[6];
    const float* D12 = (const float*)d_in[7];
    const float* bv  = (const float*)d_in[8];
    const float* bx  = (const float*)d_in[9];
    float* out = (float*)d_out;

    const int N = in_sizes[0] / DIM_NX;                 // 262144
    const int grid = (N + ROWS_CTA - 1) / ROWS_CTA;     // 2048
    const size_t smem_bytes = (size_t)SMEM_FLOATS * sizeof(float);  // 112 KB

    cudaFuncSetAttribute(renl2_kernel,
                         cudaFuncAttributeMaxDynamicSharedMemorySize,
                         (int)smem_bytes);

    renl2_kernel<<<grid, NTHREADS, smem_bytes>>>(
        x, u, A, B1, B2, C1, D11, D12, bv, bx, out, N);
}

// round 8
// speedup vs baseline: 1.5007x; 1.1347x over previous
#include <cuda_runtime.h>
#include <cuda_bf16.h>
#include <cstdint>

#define NTHREADS 256
#define MROWS    128
#define SA 336            // act / W1 / W2a row stride in BYTES (168 bf16)
#define SW 272            // w-tile / W2b row stride in BYTES (136 bf16)

// ---------------- SMEM byte layout (185.5 KB, 1 CTA/SM) ----------------
#define OFF_ACT   0        // bf16 [128 x 168]: cols 0-63 x_hi | 64-79 u_hi | 80-143 x_lo | 144-159 u_lo
#define OFF_WT    43008    // bf16 [128 x 136]: cols 0-63 w_hi | 64-127 w_lo
#define OFF_W1    77824    // bf16 [ 64 x 168]: C1_hi D12_hi | C1_lo D12_lo   (n-major rows, k contiguous)
#define OFF_W2A   99328    // bf16 [ 64 x 168]: A_hi  B2_hi  | A_lo  B2_lo
#define OFF_W2B   120832   // bf16 [ 64 x 136]: B1_hi | B1_lo
#define OFF_D11   138240   // f32 [64 x 64]
#define OFF_STAGE 154624   // f32 [128 x 68]
#define OFF_BV    189440   // f32 [64]
#define OFF_BX    189696   // f32 [64]
#define SMEM_BYTES 189952

__device__ __forceinline__ uint32_t smem_u32(const void* p) {
    uint32_t a;
    asm("{ .reg .u64 t; cvta.to.shared.u64 t, %1; cvt.u32.u64 %0, t; }" : "=r"(a) : "l"(p));
    return a;
}
__device__ __forceinline__ void ldsm4(unsigned r[4], uint32_t addr) {
    asm volatile("ldmatrix.sync.aligned.m8n8.x4.shared.b16 {%0,%1,%2,%3}, [%4];"
        : "=r"(r[0]), "=r"(r[1]), "=r"(r[2]), "=r"(r[3]) : "r"(addr));
}
__device__ __forceinline__ void mma16816(float d[4], const unsigned a[4], unsigned b0, unsigned b1) {
    asm volatile("mma.sync.aligned.m16n8k16.row.col.f32.bf16.bf16.f32 "
        "{%0,%1,%2,%3},{%4,%5,%6,%7},{%8,%9},{%0,%1,%2,%3};"
        : "+f"(d[0]), "+f"(d[1]), "+f"(d[2]), "+f"(d[3])
        : "r"(a[0]), "r"(a[1]), "r"(a[2]), "r"(a[3]), "r"(b0), "r"(b1));
}
// split two floats into packed bf16 hi pair + residual lo pair
__device__ __forceinline__ void split2(float a, float b, unsigned& hi, unsigned& lo) {
    const __nv_bfloat16 ha = __float2bfloat16_rn(a), hb = __float2bfloat16_rn(b);
    hi = (unsigned)(*reinterpret_cast<const unsigned short*>(&ha))
       | ((unsigned)(*reinterpret_cast<const unsigned short*>(&hb)) << 16);
    const __nv_bfloat162 t = __floats2bfloat162_rn(a - __bfloat162float(ha),
                                                   b - __bfloat162float(hb));
    lo = *reinterpret_cast<const unsigned*>(&t);
}
// one A-frag against all 8 n-tiles of a weight chunk cb
__device__ __forceinline__ void gemm_b8(float (*acc)[4], uint32_t blane, int strideB,
                                        int cb, const unsigned a[4]) {
    #pragma unroll
    for (int p = 0; p < 4; p++) {               // n-pairs: rows 16p..16p+15
        unsigned bf[4];
        ldsm4(bf, blane + p * 16 * strideB + 32 * cb);
        mma16816(acc[2*p + 0], a, bf[0], bf[2]);
        mma16816(acc[2*p + 1], a, bf[1], bf[3]);
    }
}

__global__ void __launch_bounds__(NTHREADS, 1)
renl2_hmma_kernel(const float* __restrict__ gx,  const float* __restrict__ gu,
                  const float* __restrict__ gA,  const float* __restrict__ gB1,
                  const float* __restrict__ gB2, const float* __restrict__ gC1,
                  const float* __restrict__ gD11,const float* __restrict__ gD12,
                  const float* __restrict__ gbv, const float* __restrict__ gbx,
                  float* __restrict__ gout, int N)
{
    extern __shared__ char smem[];
    const uint32_t sbase = smem_u32(smem);
    const int tid  = threadIdx.x;
    const int lane = tid & 31;
    const int wid  = tid >> 5;
    const int rowbase = blockIdx.x * MROWS;

    float* sD11  = reinterpret_cast<float*>(smem + OFF_D11);
    float* stage = reinterpret_cast<float*>(smem + OFF_STAGE);
    float* sbv   = reinterpret_cast<float*>(smem + OFF_BV);
    float* sbx   = reinterpret_cast<float*>(smem + OFF_BX);

    // ---------- stage weights (hi/lo split) ----------
    #pragma unroll 1
    for (int idx = tid; idx < 64 * 40; idx += NTHREADS) {   // W1 & W2a: 64 n x 80 k (pairs)
        const int n = idx / 40, k = (idx - n * 40) * 2;
        float v1a, v1b, v2a, v2b;
        if (k < 64) { v1a = gC1[n*64 + k]; v1b = gC1[n*64 + k + 1];
                      v2a = gA [n*64 + k]; v2b = gA [n*64 + k + 1]; }
        else        { v1a = gD12[n*16 + k - 64]; v1b = gD12[n*16 + k - 63];
                      v2a = gB2 [n*16 + k - 64]; v2b = gB2 [n*16 + k - 63]; }
        unsigned h1, l1, h2, l2;
        split2(v1a, v1b, h1, l1);
        split2(v2a, v2b, h2, l2);
        *reinterpret_cast<unsigned*>(smem + OFF_W1  + n*SA + 2*k)       = h1;
        *reinterpret_cast<unsigned*>(smem + OFF_W1  + n*SA + 160 + 2*k) = l1;
        *reinterpret_cast<unsigned*>(smem + OFF_W2A + n*SA + 2*k)       = h2;
        *reinterpret_cast<unsigned*>(smem + OFF_W2A + n*SA + 160 + 2*k) = l2;
    }
    #pragma unroll 1
    for (int idx = tid; idx < 64 * 32; idx += NTHREADS) {   // W2b: 64 n x 64 k (pairs)
        const int n = idx >> 5, k = (idx & 31) * 2;
        unsigned h, l;
        split2(gB1[n*64 + k], gB1[n*64 + k + 1], h, l);
        *reinterpret_cast<unsigned*>(smem + OFF_W2B + n*SW + 2*k)       = h;
        *reinterpret_cast<unsigned*>(smem + OFF_W2B + n*SW + 128 + 2*k) = l;
    }
    #pragma unroll 1
    for (int idx = tid; idx < 4096; idx += NTHREADS) sD11[idx] = gD11[idx];
    if (tid < 64) { sbv[tid] = gbv[tid]; sbx[tid] = gbx[tid]; }

    // ---------- stage activations (hi/lo split) ----------
    const float4* gx4 = reinterpret_cast<const float4*>(gx);
    #pragma unroll 1
    for (int idx = tid; idx < MROWS * 16; idx += NTHREADS) {
        const int row = idx >> 4, q = idx & 15;
        if (rowbase + row >= N) continue;
        const float4 v = gx4[(size_t)(rowbase + row) * 16 + q];
        unsigned h0, l0, h1, l1;
        split2(v.x, v.y, h0, l0);
        split2(v.z, v.w, h1, l1);
        char* rp = smem + OFF_ACT + row * SA;
        *reinterpret_cast<unsigned*>(rp + 8*q)           = h0;
        *reinterpret_cast<unsigned*>(rp + 8*q + 4)       = h1;
        *reinterpret_cast<unsigned*>(rp + 160 + 8*q)     = l0;
        *reinterpret_cast<unsigned*>(rp + 160 + 8*q + 4) = l1;
    }
    const float4* gu4 = reinterpret_cast<const float4*>(gu);
    #pragma unroll 1
    for (int idx = tid; idx < MROWS * 4; idx += NTHREADS) {
        const int row = idx >> 2, q = idx & 3;
        if (rowbase + row >= N) continue;
        const float4 v = gu4[(size_t)(rowbase + row) * 4 + q];
        unsigned h0, l0, h1, l1;
        split2(v.x, v.y, h0, l0);
        split2(v.z, v.w, h1, l1);
        char* rp = smem + OFF_ACT + row * SA;
        *reinterpret_cast<unsigned*>(rp + 128 + 8*q)     = h0;   // col 64+4q (hi)
        *reinterpret_cast<unsigned*>(rp + 128 + 8*q + 4) = h1;
        *reinterpret_cast<unsigned*>(rp + 288 + 8*q)     = l0;   // col 144+4q (lo)
        *reinterpret_cast<unsigned*>(rp + 288 + 8*q + 4) = l1;
    }
    __syncthreads();

    // per-lane ldmatrix base addresses
    const uint32_t a_act  = sbase + OFF_ACT + (16*wid + (lane & 15)) * SA + 16 * (lane >> 4);
    const uint32_t a_wt   = sbase + OFF_WT  + (16*wid + (lane & 15)) * SW + 16 * (lane >> 4);
    const uint32_t b_w1   = sbase + OFF_W1  + (lane & 15) * SA + 16 * (lane >> 4);
    const uint32_t b_w2a  = sbase + OFF_W2A + (lane & 15) * SA + 16 * (lane >> 4);
    const uint32_t b_w2b  = sbase + OFF_W2B + (lane & 15) * SW + 16 * (lane >> 4);

    const int q  = lane & 3;        // accum col group
    const int rh = lane >> 2;       // accum row within tile

    // ========== GEMM1: base = [act] x W1^T ==========
    {
        float acc[8][4] = {};
        #pragma unroll
        for (int c = 0; c < 5; c++) {
            unsigned ah[4], al[4];
            ldsm4(ah, a_act + 32 * c);              // act hi chunk c
            gemm_b8(acc, b_w1, SA, c,     ah);      // hi . hi
            gemm_b8(acc, b_w1, SA, 5 + c, ah);      // hi . lo
            ldsm4(al, a_act + 32 * (5 + c));        // act lo chunk c
            gemm_b8(acc, b_w1, SA, c,     al);      // lo . hi
        }
        #pragma unroll
        for (int n = 0; n < 8; n++) {
            const int c0 = 8*n + 2*q;
            *reinterpret_cast<float2*>(stage + (16*wid + rh    ) * 68 + c0) = make_float2(acc[n][0], acc[n][1]);
            *reinterpret_cast<float2*>(stage + (16*wid + rh + 8) * 68 + c0) = make_float2(acc[n][2], acc[n][3]);
        }
    }
    __syncthreads();

    // ========== triangular solve with ReLU (one thread per row) ==========
    if (tid < MROWS) {
        const int row = tid;
        float wv[64];
        const float4* brow = reinterpret_cast<const float4*>(stage + row * 68);
        const float4* bvp  = reinterpret_cast<const float4*>(sbv);
        #pragma unroll
        for (int g = 0; g < 16; g++) {
            const float4 b = brow[g], v = bvp[g];
            wv[4*g+0] = b.x + v.x; wv[4*g+1] = b.y + v.y;
            wv[4*g+2] = b.z + v.z; wv[4*g+3] = b.w + v.w;
        }
        wv[0] = fmaxf(wv[0], 0.0f);
        #pragma unroll
        for (int i = 1; i < 64; i++) {
            const float4* drow = reinterpret_cast<const float4*>(sD11 + i * 64);
            float a0 = wv[i], a1 = 0.0f, a2 = 0.0f, a3 = 0.0f;
            const int ng = (i >> 2) + 1;
            #pragma unroll
            for (int g = 0; g < 16; g++) {
                if (g >= ng) break;                  // strict-lower zeros pad the tail
                const float4 d = drow[g];
                a0 = fmaf(d.x, wv[4*g+0], a0);
                a1 = fmaf(d.y, wv[4*g+1], a1);
                a2 = fmaf(d.z, wv[4*g+2], a2);
                a3 = fmaf(d.w, wv[4*g+3], a3);
            }
            wv[i] = fmaxf((a0 + a1) + (a2 + a3), 0.0f);
        }
        // write w as bf16 hi (cols 0-63) / lo (cols 64-127)
        char* wt = smem + OFF_WT + row * SW;
        #pragma unroll
        for (int b8 = 0; b8 < 8; b8++) {
            unsigned hp[4], lp[4];
            #pragma unroll
            for (int t = 0; t < 4; t++)
                split2(wv[8*b8 + 2*t], wv[8*b8 + 2*t + 1], hp[t], lp[t]);
            *reinterpret_cast<uint4*>(wt + 16*b8)       = make_uint4(hp[0], hp[1], hp[2], hp[3]);
            *reinterpret_cast<uint4*>(wt + 128 + 16*b8) = make_uint4(lp[0], lp[1], lp[2], lp[3]);
        }
    }
    __syncthreads();

    // ========== GEMM2: out = [act] x W2a^T + [w] x B1^T ==========
    {
        float acc[8][4] = {};
        #pragma unroll
        for (int c = 0; c < 5; c++) {
            unsigned ah[4], al[4];
            ldsm4(ah, a_act + 32 * c);
            gemm_b8(acc, b_w2a, SA, c,     ah);
            gemm_b8(acc, b_w2a, SA, 5 + c, ah);
            ldsm4(al, a_act + 32 * (5 + c));
            gemm_b8(acc, b_w2a, SA, c,     al);
        }
        #pragma unroll
        for (int c = 0; c < 4; c++) {
            unsigned ah[4], al[4];
            ldsm4(ah, a_wt + 32 * c);               // w hi chunk c
            gemm_b8(acc, b_w2b, SW, c,     ah);
            gemm_b8(acc, b_w2b, SW, 4 + c, ah);
            ldsm4(al, a_wt + 32 * (4 + c));         // w lo chunk c
            gemm_b8(acc, b_w2b, SW, c,     al);
        }
        // epilogue: + bx, stage for coalesced store
        #pragma unroll
        for (int n = 0; n < 8; n++) {
            const int c0 = 8*n + 2*q;
            const float2 bx2 = *reinterpret_cast<const float2*>(sbx + c0);
            *reinterpret_cast<float2*>(stage + (16*wid + rh    ) * 68 + c0) =
                make_float2(acc[n][0] + bx2.x, acc[n][1] + bx2.y);
            *reinterpret_cast<float2*>(stage + (16*wid + rh + 8) * 68 + c0) =
                make_float2(acc[n][2] + bx2.x, acc[n][3] + bx2.y);
        }
    }
    __syncthreads();

    // ---------- coalesced store ----------
    float4* gout4 = reinterpret_cast<float4*>(gout);
    #pragma unroll 1
    for (int idx = tid; idx < MROWS * 16; idx += NTHREADS) {
        const int row = idx >> 4, c = idx & 15;
        if (rowbase + row < N)
            gout4[(size_t)(rowbase + row) * 16 + c] =
                *reinterpret_cast<float4*>(stage + row * 68 + 4*c);
    }
}

extern "C" void kernel_launch(void* const* d_in, const int* in_sizes, int n_in,
                              void* d_out, int out_size) {
    (void)n_in; (void)out_size;
    const float* x   = (const float*)d_in[0];
    const float* u   = (const float*)d_in[1];
    const float* A   = (const float*)d_in[2];
    const float* B1  = (const float*)d_in[3];
    const float* B2  = (const float*)d_in[4];
    const float* C1  = (const float*)d_in[5];
    const float* D11 = (const float*)d_in[6];
    const float* D12 = (const float*)d_in[7];
    const float* bv  = (const float*)d_in[8];
    const float* bx  = (const float*)d_in[9];
    float* out = (float*)d_out;

    const int N = in_sizes[0] / 64;                     // 262144
    const int grid = (N + MROWS - 1) / MROWS;           // 2048

    cudaFuncSetAttribute(renl2_hmma_kernel,
                         cudaFuncAttributeMaxDynamicSharedMemorySize,
                         SMEM_BYTES);

    renl2_hmma_kernel<<<grid, NTHREADS, SMEM_BYTES>>>(
        x, u, A, B1, B2, C1, D11, D12, bv, bx, out, N);
}

// round 9
// speedup vs baseline: 1.6573x; 1.1043x over previous
#include <cuda_runtime.h>
#include <cuda_bf16.h>
#include <cstdint>

#define NTHREADS 256
#define MROWS    128
#define SA 336            // act / W1 / W2a row stride in BYTES (168 bf16)
#define SW 272            // w-tile / W2b row stride in BYTES (136 bf16)

// ---------------- SMEM byte layout (185.5 KB, 1 CTA/SM) ----------------
#define OFF_W1    0        // bf16 [64 x 168]: C1_hi D12_hi | C1_lo D12_lo
#define OFF_W2A   21504    // bf16 [64 x 168]: A_hi  B2_hi  | A_lo  B2_lo
#define OFF_W2B   43008    // bf16 [64 x 136]: B1_hi | B1_lo
#define OFF_D11   60416    // f32 [64 x 64]
#define OFF_BV    76800    // f32 [64]
#define OFF_BX    77056    // f32 [64]
#define OFF_ACT   77312    // bf16 [128 x 168]: x_hi | u_hi | x_lo | u_lo
#define OFF_WT    120320   // bf16 [128 x 136]: w_hi | w_lo
#define OFF_STAGE 155136   // f32 [128 x 68]
#define SMEM_BYTES 189952

// pre-split weight tiles in global scratch (written by prep kernel)
__device__ __align__(16) unsigned char gW1s [21504];
__device__ __align__(16) unsigned char gW2As[21504];
__device__ __align__(16) unsigned char gW2Bs[17408];

__device__ __forceinline__ uint32_t smem_u32(const void* p) {
    uint32_t a;
    asm("{ .reg .u64 t; cvta.to.shared.u64 t, %1; cvt.u32.u64 %0, t; }" : "=r"(a) : "l"(p));
    return a;
}
__device__ __forceinline__ void ldsm4(unsigned r[4], uint32_t addr) {
    asm volatile("ldmatrix.sync.aligned.m8n8.x4.shared.b16 {%0,%1,%2,%3}, [%4];"
        : "=r"(r[0]), "=r"(r[1]), "=r"(r[2]), "=r"(r[3]) : "r"(addr));
}
__device__ __forceinline__ void mma16816(float d[4], const unsigned a[4], unsigned b0, unsigned b1) {
    asm volatile("mma.sync.aligned.m16n8k16.row.col.f32.bf16.bf16.f32 "
        "{%0,%1,%2,%3},{%4,%5,%6,%7},{%8,%9},{%0,%1,%2,%3};"
        : "+f"(d[0]), "+f"(d[1]), "+f"(d[2]), "+f"(d[3])
        : "r"(a[0]), "r"(a[1]), "r"(a[2]), "r"(a[3]), "r"(b0), "r"(b1));
}
__device__ __forceinline__ void split2(float a, float b, unsigned& hi, unsigned& lo) {
    const __nv_bfloat16 ha = __float2bfloat16_rn(a), hb = __float2bfloat16_rn(b);
    hi = (unsigned)(*reinterpret_cast<const unsigned short*>(&ha))
       | ((unsigned)(*reinterpret_cast<const unsigned short*>(&hb)) << 16);
    const __nv_bfloat162 t = __floats2bfloat162_rn(a - __bfloat162float(ha),
                                                   b - __bfloat162float(hb));
    lo = *reinterpret_cast<const unsigned*>(&t);
}
__device__ __forceinline__ void gemm_b8(float (*acc)[4], uint32_t blane, int strideB,
                                        int cb, const unsigned a[4]) {
    #pragma unroll
    for (int p = 0; p < 4; p++) {
        unsigned bf[4];
        ldsm4(bf, blane + p * 16 * strideB + 32 * cb);
        mma16816(acc[2*p + 0], a, bf[0], bf[2]);
        mma16816(acc[2*p + 1], a, bf[1], bf[3]);
    }
}

// ---------------- prep kernel: split weights once ----------------
__global__ void __launch_bounds__(256)
renl2_prep_kernel(const float* __restrict__ gA,  const float* __restrict__ gB1,
                  const float* __restrict__ gB2, const float* __restrict__ gC1,
                  const float* __restrict__ gD12)
{
    const int tid = threadIdx.x;
    #pragma unroll 1
    for (int idx = tid; idx < 64 * 40; idx += 256) {        // W1 & W2a: 64 n x 80 k-pairs
        const int n = idx / 40, k = (idx - n * 40) * 2;
        float v1a, v1b, v2a, v2b;
        if (k < 64) { v1a = gC1[n*64 + k]; v1b = gC1[n*64 + k + 1];
                      v2a = gA [n*64 + k]; v2b = gA [n*64 + k + 1]; }
        else        { v1a = gD12[n*16 + k - 64]; v1b = gD12[n*16 + k - 63];
                      v2a = gB2 [n*16 + k - 64]; v2b = gB2 [n*16 + k - 63]; }
        unsigned h1, l1, h2, l2;
        split2(v1a, v1b, h1, l1);
        split2(v2a, v2b, h2, l2);
        *reinterpret_cast<unsigned*>(gW1s  + n*SA + 2*k)       = h1;
        *reinterpret_cast<unsigned*>(gW1s  + n*SA + 160 + 2*k) = l1;
        *reinterpret_cast<unsigned*>(gW2As + n*SA + 2*k)       = h2;
        *reinterpret_cast<unsigned*>(gW2As + n*SA + 160 + 2*k) = l2;
    }
    #pragma unroll 1
    for (int idx = tid; idx < 64 * 32; idx += 256) {        // W2b: 64 n x 64 k-pairs
        const int n = idx >> 5, k = (idx & 31) * 2;
        unsigned h, l;
        split2(gB1[n*64 + k], gB1[n*64 + k + 1], h, l);
        *reinterpret_cast<unsigned*>(gW2Bs + n*SW + 2*k)       = h;
        *reinterpret_cast<unsigned*>(gW2Bs + n*SW + 128 + 2*k) = l;
    }
}

// ---------------- main kernel ----------------
__global__ void __launch_bounds__(NTHREADS, 1)
renl2_hmma_kernel(const float* __restrict__ gx,  const float* __restrict__ gu,
                  const float* __restrict__ gD11,
                  const float* __restrict__ gbv, const float* __restrict__ gbx,
                  float* __restrict__ gout, int N)
{
    extern __shared__ char smem[];
    const uint32_t sbase = smem_u32(smem);
    const int tid  = threadIdx.x;
    const int lane = tid & 31;
    const int wid  = tid >> 5;
    const int rowbase = blockIdx.x * MROWS;

    float* sD11  = reinterpret_cast<float*>(smem + OFF_D11);
    float* stage = reinterpret_cast<float*>(smem + OFF_STAGE);
    float* sbv   = reinterpret_cast<float*>(smem + OFF_BV);
    float* sbx   = reinterpret_cast<float*>(smem + OFF_BX);

    // ---------- copy pre-split weights + D11 + biases (plain uint4 copies) ----------
    {
        const uint4* s1 = reinterpret_cast<const uint4*>(gW1s);
        const uint4* s2 = reinterpret_cast<const uint4*>(gW2As);
        uint4* d1 = reinterpret_cast<uint4*>(smem + OFF_W1);
        uint4* d2 = reinterpret_cast<uint4*>(smem + OFF_W2A);
        #pragma unroll 1
        for (int i = tid; i < 21504/16; i += NTHREADS) { d1[i] = s1[i]; d2[i] = s2[i]; }
        const uint4* s3 = reinterpret_cast<const uint4*>(gW2Bs);
        uint4* d3 = reinterpret_cast<uint4*>(smem + OFF_W2B);
        #pragma unroll 1
        for (int i = tid; i < 17408/16; i += NTHREADS) d3[i] = s3[i];
        const uint4* s4 = reinterpret_cast<const uint4*>(gD11);
        uint4* d4 = reinterpret_cast<uint4*>(smem + OFF_D11);
        #pragma unroll 1
        for (int i = tid; i < 16384/16; i += NTHREADS) d4[i] = s4[i];
        if (tid < 64) { sbv[tid] = gbv[tid]; sbx[tid] = gbx[tid]; }
    }

    // ---------- stage activations (hi/lo split) ----------
    const float4* gx4 = reinterpret_cast<const float4*>(gx);
    #pragma unroll 1
    for (int idx = tid; idx < MROWS * 16; idx += NTHREADS) {
        const int row = idx >> 4, q = idx & 15;
        if (rowbase + row >= N) continue;
        const float4 v = gx4[(size_t)(rowbase + row) * 16 + q];
        unsigned h0, l0, h1, l1;
        split2(v.x, v.y, h0, l0);
        split2(v.z, v.w, h1, l1);
        char* rp = smem + OFF_ACT + row * SA;
        *reinterpret_cast<unsigned*>(rp + 8*q)           = h0;
        *reinterpret_cast<unsigned*>(rp + 8*q + 4)       = h1;
        *reinterpret_cast<unsigned*>(rp + 160 + 8*q)     = l0;
        *reinterpret_cast<unsigned*>(rp + 160 + 8*q + 4) = l1;
    }
    const float4* gu4 = reinterpret_cast<const float4*>(gu);
    #pragma unroll 1
    for (int idx = tid; idx < MROWS * 4; idx += NTHREADS) {
        const int row = idx >> 2, q = idx & 3;
        if (rowbase + row >= N) continue;
        const float4 v = gu4[(size_t)(rowbase + row) * 4 + q];
        unsigned h0, l0, h1, l1;
        split2(v.x, v.y, h0, l0);
        split2(v.z, v.w, h1, l1);
        char* rp = smem + OFF_ACT + row * SA;
        *reinterpret_cast<unsigned*>(rp + 128 + 8*q)     = h0;
        *reinterpret_cast<unsigned*>(rp + 128 + 8*q + 4) = h1;
        *reinterpret_cast<unsigned*>(rp + 288 + 8*q)     = l0;
        *reinterpret_cast<unsigned*>(rp + 288 + 8*q + 4) = l1;
    }
    __syncthreads();   // ONLY block-wide barrier: shared tiles ready

    // ---------- per-warp independent pipeline from here on ----------
    const uint32_t a_act = sbase + OFF_ACT + (16*wid + (lane & 15)) * SA + 16 * (lane >> 4);
    const uint32_t a_wt  = sbase + OFF_WT  + (16*wid + (lane & 15)) * SW + 16 * (lane >> 4);
    const uint32_t b_w1  = sbase + OFF_W1  + (lane & 15) * SA + 16 * (lane >> 4);
    const uint32_t b_w2a = sbase + OFF_W2A + (lane & 15) * SA + 16 * (lane >> 4);
    const uint32_t b_w2b = sbase + OFF_W2B + (lane & 15) * SW + 16 * (lane >> 4);

    const int q  = lane & 3;
    const int rh = lane >> 2;

    // ===== GEMM1: base = [act] x W1^T (own 16-row tile) =====
    {
        float acc[8][4] = {};
        #pragma unroll
        for (int c = 0; c < 5; c++) {
            unsigned ah[4], al[4];
            ldsm4(ah, a_act + 32 * c);
            gemm_b8(acc, b_w1, SA, c,     ah);      // hi . hi
            gemm_b8(acc, b_w1, SA, 5 + c, ah);      // hi . lo
            ldsm4(al, a_act + 32 * (5 + c));
            gemm_b8(acc, b_w1, SA, c,     al);      // lo . hi
        }
        #pragma unroll
        for (int n = 0; n < 8; n++) {
            const int c0 = 8*n + 2*q;
            *reinterpret_cast<float2*>(stage + (16*wid + rh    ) * 68 + c0) = make_float2(acc[n][0], acc[n][1]);
            *reinterpret_cast<float2*>(stage + (16*wid + rh + 8) * 68 + c0) = make_float2(acc[n][2], acc[n][3]);
        }
    }
    __syncwarp();

    // ===== triangular solve with ReLU: lanes 0-15, one row each =====
    if (lane < 16) {
        const int row = 16*wid + lane;
        float wv[64];
        const float4* brow = reinterpret_cast<const float4*>(stage + row * 68);
        const float4* bvp  = reinterpret_cast<const float4*>(sbv);
        #pragma unroll
        for (int g = 0; g < 16; g++) {
            const float4 b = brow[g], v = bvp[g];
            wv[4*g+0] = b.x + v.x; wv[4*g+1] = b.y + v.y;
            wv[4*g+2] = b.z + v.z; wv[4*g+3] = b.w + v.w;
        }
        wv[0] = fmaxf(wv[0], 0.0f);
        #pragma unroll
        for (int i = 1; i < 64; i++) {
            const float4* drow = reinterpret_cast<const float4*>(sD11 + i * 64);
            float a0 = wv[i], a1 = 0.0f, a2 = 0.0f, a3 = 0.0f;
            const int ng = (i >> 2) + 1;
            #pragma unroll
            for (int g = 0; g < 16; g++) {
                if (g >= ng) break;                  // strict-lower zeros pad the tail
                const float4 d = drow[g];
                a0 = fmaf(d.x, wv[4*g+0], a0);
                a1 = fmaf(d.y, wv[4*g+1], a1);
                a2 = fmaf(d.z, wv[4*g+2], a2);
                a3 = fmaf(d.w, wv[4*g+3], a3);
            }
            wv[i] = fmaxf((a0 + a1) + (a2 + a3), 0.0f);
        }
        char* wt = smem + OFF_WT + row * SW;
        #pragma unroll
        for (int b8 = 0; b8 < 8; b8++) {
            unsigned hp[4], lp[4];
            #pragma unroll
            for (int t = 0; t < 4; t++)
                split2(wv[8*b8 + 2*t], wv[8*b8 + 2*t + 1], hp[t], lp[t]);
            *reinterpret_cast<uint4*>(wt + 16*b8)       = make_uint4(hp[0], hp[1], hp[2], hp[3]);
            *reinterpret_cast<uint4*>(wt + 128 + 16*b8) = make_uint4(lp[0], lp[1], lp[2], lp[3]);
        }
    }
    __syncwarp();

    // ===== GEMM2: out = [act] x W2a^T + [w] x B1^T (own tile) =====
    {
        float acc[8][4] = {};
        #pragma unroll
        for (int c = 0; c < 5; c++) {
            unsigned ah[4], al[4];
            ldsm4(ah, a_act + 32 * c);
            gemm_b8(acc, b_w2a, SA, c,     ah);
            gemm_b8(acc, b_w2a, SA, 5 + c, ah);
            ldsm4(al, a_act + 32 * (5 + c));
            gemm_b8(acc, b_w2a, SA, c,     al);
        }
        #pragma unroll
        for (int c = 0; c < 4; c++) {
            unsigned ah[4], al[4];
            ldsm4(ah, a_wt + 32 * c);
            gemm_b8(acc, b_w2b, SW, c,     ah);
            gemm_b8(acc, b_w2b, SW, 4 + c, ah);
            ldsm4(al, a_wt + 32 * (4 + c));
            gemm_b8(acc, b_w2b, SW, c,     al);
        }
        #pragma unroll
        for (int n = 0; n < 8; n++) {
            const int c0 = 8*n + 2*q;
            const float2 bx2 = *reinterpret_cast<const float2*>(sbx + c0);
            *reinterpret_cast<float2*>(stage + (16*wid + rh    ) * 68 + c0) =
                make_float2(acc[n][0] + bx2.x, acc[n][1] + bx2.y);
            *reinterpret_cast<float2*>(stage + (16*wid + rh + 8) * 68 + c0) =
                make_float2(acc[n][2] + bx2.x, acc[n][3] + bx2.y);
        }
    }
    __syncwarp();

    // ---------- store own 16 rows (coalesced within 2-row groups) ----------
    float4* gout4 = reinterpret_cast<float4*>(gout);
    #pragma unroll
    for (int i = 0; i < 8; i++) {
        const int idx = i * 32 + lane;
        const int row = 16*wid + (idx >> 4), c = idx & 15;
        if (rowbase + row < N)
            gout4[(size_t)(rowbase + row) * 16 + c] =
                *reinterpret_cast<float4*>(stage + row * 68 + 4*c);
    }
}

extern "C" void kernel_launch(void* const* d_in, const int* in_sizes, int n_in,
                              void* d_out, int out_size) {
    (void)n_in; (void)out_size;
    const float* x   = (const float*)d_in[0];
    const float* u   = (const float*)d_in[1];
    const float* A   = (const float*)d_in[2];
    const float* B1  = (const float*)d_in[3];
    const float* B2  = (const float*)d_in[4];
    const float* C1  = (const float*)d_in[5];
    const float* D11 = (const float*)d_in[6];
    const float* D12 = (const float*)d_in[7];
    const float* bv  = (const float*)d_in[8];
    const float* bx  = (const float*)d_in[9];
    float* out = (float*)d_out;

    const int N = in_sizes[0] / 64;                     // 262144
    const int grid = (N + MROWS - 1) / MROWS;           // 2048

    renl2_prep_kernel<<<1, 256>>>(A, B1, B2, C1, D12);

    cudaFuncSetAttribute(renl2_hmma_kernel,
                         cudaFuncAttributeMaxDynamicSharedMemorySize,
                         SMEM_BYTES);
    renl2_hmma_kernel<<<grid, NTHREADS, SMEM_BYTES>>>(
        x, u, D11, bv, bx, out, N);
}

// round 10
// speedup vs baseline: 2.1491x; 1.2967x over previous
#include <cuda_runtime.h>
#include <cuda_bf16.h>
#include <cstdint>

#define NTHREADS 512
#define MROWS    256
#define SA 336            // act / W1 / W2a row stride in BYTES (168 bf16)
#define SW 272            // stage(f32x68) / wt / W2B row stride in BYTES

// ---------------- SMEM byte layout (220 KB, 1 CTA/SM, 16 warps) ----------------
#define OFF_W1    0        // bf16 [64 x 168]: C1_hi D12_hi | C1_lo D12_lo
#define OFF_W2A   21504    // bf16 [64 x 168]: A_hi  B2_hi  | A_lo  B2_lo
#define OFF_W2B   43008    // bf16 [64 x 136]: B1_hi | B1_lo
#define OFF_D11P  60416    // packed lower-tri f32, 8704 B
#define OFF_BV    69120    // f32 [64]
#define OFF_BX    69376    // f32 [64]
#define OFF_ACT   69632    // bf16 [256 x 168]: x_hi | u_hi | x_lo | u_lo
#define OFF_S     155648   // ALIASED: stage f32[256 x 68] / wt bf16[256 x 136]
#define SMEM_BYTES 225280

// packed D11 row offset in float4 units: rows 1..i-1 each hold (j>>2)+1 groups
__device__ __host__ __forceinline__ int d11_off4(int i) {
    const int m = i - 1, qq = m >> 2, rr = m & 3;
    return m + 2 * qq * (qq - 1) + qq * (rr + 1);
}

// pre-split weight tiles in global scratch (written by prep kernel)
__device__ __align__(16) unsigned char gW1s [21504];
__device__ __align__(16) unsigned char gW2As[21504];
__device__ __align__(16) unsigned char gW2Bs[17408];

__device__ __forceinline__ uint32_t smem_u32(const void* p) {
    uint32_t a;
    asm("{ .reg .u64 t; cvta.to.shared.u64 t, %1; cvt.u32.u64 %0, t; }" : "=r"(a) : "l"(p));
    return a;
}
__device__ __forceinline__ void ldsm4(unsigned r[4], uint32_t addr) {
    asm volatile("ldmatrix.sync.aligned.m8n8.x4.shared.b16 {%0,%1,%2,%3}, [%4];"
        : "=r"(r[0]), "=r"(r[1]), "=r"(r[2]), "=r"(r[3]) : "r"(addr));
}
__device__ __forceinline__ void mma16816(float d[4], const unsigned a[4], unsigned b0, unsigned b1) {
    asm volatile("mma.sync.aligned.m16n8k16.row.col.f32.bf16.bf16.f32 "
        "{%0,%1,%2,%3},{%4,%5,%6,%7},{%8,%9},{%0,%1,%2,%3};"
        : "+f"(d[0]), "+f"(d[1]), "+f"(d[2]), "+f"(d[3])
        : "r"(a[0]), "r"(a[1]), "r"(a[2]), "r"(a[3]), "r"(b0), "r"(b1));
}
__device__ __forceinline__ void split2(float a, float b, unsigned& hi, unsigned& lo) {
    const __nv_bfloat16 ha = __float2bfloat16_rn(a), hb = __float2bfloat16_rn(b);
    hi = (unsigned)(*reinterpret_cast<const unsigned short*>(&ha))
       | ((unsigned)(*reinterpret_cast<const unsigned short*>(&hb)) << 16);
    const __nv_bfloat162 t = __floats2bfloat162_rn(a - __bfloat162float(ha),
                                                   b - __bfloat162float(hb));
    lo = *reinterpret_cast<const unsigned*>(&t);
}
__device__ __forceinline__ void gemm_b8(float (*acc)[4], uint32_t blane, int strideB,
                                        int cb, const unsigned a[4]) {
    #pragma unroll
    for (int p = 0; p < 4; p++) {
        unsigned bf[4];
        ldsm4(bf, blane + p * 16 * strideB + 32 * cb);
        mma16816(acc[2*p + 0], a, bf[0], bf[2]);
        mma16816(acc[2*p + 1], a, bf[1], bf[3]);
    }
}

// ---------------- prep kernel: split weights once ----------------
__global__ void __launch_bounds__(256)
renl2_prep_kernel(const float* __restrict__ gA,  const float* __restrict__ gB1,
                  const float* __restrict__ gB2, const float* __restrict__ gC1,
                  const float* __restrict__ gD12)
{
    const int tid = threadIdx.x;
    #pragma unroll 1
    for (int idx = tid; idx < 64 * 40; idx += 256) {
        const int n = idx / 40, k = (idx - n * 40) * 2;
        float v1a, v1b, v2a, v2b;
        if (k < 64) { v1a = gC1[n*64 + k]; v1b = gC1[n*64 + k + 1];
                      v2a = gA [n*64 + k]; v2b = gA [n*64 + k + 1]; }
        else        { v1a = gD12[n*16 + k - 64]; v1b = gD12[n*16 + k - 63];
                      v2a = gB2 [n*16 + k - 64]; v2b = gB2 [n*16 + k - 63]; }
        unsigned h1, l1, h2, l2;
        split2(v1a, v1b, h1, l1);
        split2(v2a, v2b, h2, l2);
        *reinterpret_cast<unsigned*>(gW1s  + n*SA + 2*k)       = h1;
        *reinterpret_cast<unsigned*>(gW1s  + n*SA + 160 + 2*k) = l1;
        *reinterpret_cast<unsigned*>(gW2As + n*SA + 2*k)       = h2;
        *reinterpret_cast<unsigned*>(gW2As + n*SA + 160 + 2*k) = l2;
    }
    #pragma unroll 1
    for (int idx = tid; idx < 64 * 32; idx += 256) {
        const int n = idx >> 5, k = (idx & 31) * 2;
        unsigned h, l;
        split2(gB1[n*64 + k], gB1[n*64 + k + 1], h, l);
        *reinterpret_cast<unsigned*>(gW2Bs + n*SW + 2*k)       = h;
        *reinterpret_cast<unsigned*>(gW2Bs + n*SW + 128 + 2*k) = l;
    }
}

// ---------------- main kernel ----------------
__global__ void __launch_bounds__(NTHREADS, 1)
renl2_hmma_kernel(const float* __restrict__ gx,  const float* __restrict__ gu,
                  const float* __restrict__ gD11,
                  const float* __restrict__ gbv, const float* __restrict__ gbx,
                  float* __restrict__ gout, int N)
{
    extern __shared__ char smem[];
    const uint32_t sbase = smem_u32(smem);
    const int tid  = threadIdx.x;
    const int lane = tid & 31;
    const int wid  = tid >> 5;
    const int rowbase = blockIdx.x * MROWS;

    float* stage   = reinterpret_cast<float*>(smem + OFF_S);    // aliased with wt
    float* sbv     = reinterpret_cast<float*>(smem + OFF_BV);
    float* sbx     = reinterpret_cast<float*>(smem + OFF_BX);
    float4* sD11p4 = reinterpret_cast<float4*>(smem + OFF_D11P);

    // ---------- copy pre-split weights + packed D11 + biases ----------
    {
        const uint4* s1 = reinterpret_cast<const uint4*>(gW1s);
        const uint4* s2 = reinterpret_cast<const uint4*>(gW2As);
        uint4* d1 = reinterpret_cast<uint4*>(smem + OFF_W1);
        uint4* d2 = reinterpret_cast<uint4*>(smem + OFF_W2A);
        #pragma unroll 1
        for (int i = tid; i < 21504/16; i += NTHREADS) { d1[i] = s1[i]; d2[i] = s2[i]; }
        const uint4* s3 = reinterpret_cast<const uint4*>(gW2Bs);
        uint4* d3 = reinterpret_cast<uint4*>(smem + OFF_W2B);
        #pragma unroll 1
        for (int i = tid; i < 17408/16; i += NTHREADS) d3[i] = s3[i];
        if (tid >= 1 && tid < 64) {                  // packed D11 row copy
            const int i = tid, ng = (i >> 2) + 1;
            const float4* src = reinterpret_cast<const float4*>(gD11 + i * 64);
            float4* dst = sD11p4 + d11_off4(i);
            for (int g = 0; g < ng; g++) dst[g] = src[g];
        }
        if (tid >= 64 && tid < 128) sbv[tid - 64] = gbv[tid - 64];
        if (tid >= 128 && tid < 192) sbx[tid - 128] = gbx[tid - 128];
    }

    // ---------- stage activations (hi/lo split) ----------
    const float4* gx4 = reinterpret_cast<const float4*>(gx);
    #pragma unroll 1
    for (int idx = tid; idx < MROWS * 16; idx += NTHREADS) {
        const int row = idx >> 4, q = idx & 15;
        if (rowbase + row >= N) continue;
        const float4 v = gx4[(size_t)(rowbase + row) * 16 + q];
        unsigned h0, l0, h1, l1;
        split2(v.x, v.y, h0, l0);
        split2(v.z, v.w, h1, l1);
        char* rp = smem + OFF_ACT + row * SA;
        *reinterpret_cast<unsigned*>(rp + 8*q)           = h0;
        *reinterpret_cast<unsigned*>(rp + 8*q + 4)       = h1;
        *reinterpret_cast<unsigned*>(rp + 160 + 8*q)     = l0;
        *reinterpret_cast<unsigned*>(rp + 160 + 8*q + 4) = l1;
    }
    const float4* gu4 = reinterpret_cast<const float4*>(gu);
    #pragma unroll 1
    for (int idx = tid; idx < MROWS * 4; idx += NTHREADS) {
        const int row = idx >> 2, q = idx & 3;
        if (rowbase + row >= N) continue;
        const float4 v = gu4[(size_t)(rowbase + row) * 4 + q];
        unsigned h0, l0, h1, l1;
        split2(v.x, v.y, h0, l0);
        split2(v.z, v.w, h1, l1);
        char* rp = smem + OFF_ACT + row * SA;
        *reinterpret_cast<unsigned*>(rp + 128 + 8*q)     = h0;
        *reinterpret_cast<unsigned*>(rp + 128 + 8*q + 4) = h1;
        *reinterpret_cast<unsigned*>(rp + 288 + 8*q)     = l0;
        *reinterpret_cast<unsigned*>(rp + 288 + 8*q + 4) = l1;
    }
    __syncthreads();   // ONLY block-wide barrier

    // ---------- per-warp independent pipeline (warp owns rows 16*wid..+15) ----------
    const uint32_t a_act = sbase + OFF_ACT + (16*wid + (lane & 15)) * SA + 16 * (lane >> 4);
    const uint32_t a_wt  = sbase + OFF_S   + (16*wid + (lane & 15)) * SW + 16 * (lane >> 4);
    const uint32_t b_w1  = sbase + OFF_W1  + (lane & 15) * SA + 16 * (lane >> 4);
    const uint32_t b_w2a = sbase + OFF_W2A + (lane & 15) * SA + 16 * (lane >> 4);
    const uint32_t b_w2b = sbase + OFF_W2B + (lane & 15) * SW + 16 * (lane >> 4);

    const int q  = lane & 3;
    const int rh = lane >> 2;

    // ===== GEMM1: base = [act] x W1^T =====
    {
        float acc[8][4] = {};
        #pragma unroll
        for (int c = 0; c < 5; c++) {
            unsigned ah[4], al[4];
            ldsm4(ah, a_act + 32 * c);
            gemm_b8(acc, b_w1, SA, c,     ah);      // hi . hi
            gemm_b8(acc, b_w1, SA, 5 + c, ah);      // hi . lo
            ldsm4(al, a_act + 32 * (5 + c));
            gemm_b8(acc, b_w1, SA, c,     al);      // lo . hi
        }
        #pragma unroll
        for (int n = 0; n < 8; n++) {
            const int c0 = 8*n + 2*q;
            *reinterpret_cast<float2*>(stage + (16*wid + rh    ) * 68 + c0) = make_float2(acc[n][0], acc[n][1]);
            *reinterpret_cast<float2*>(stage + (16*wid + rh + 8) * 68 + c0) = make_float2(acc[n][2], acc[n][3]);
        }
    }
    __syncwarp();

    // ===== triangular solve with ReLU: lanes 0-15, one row each =====
    // Reads its full stage row, then overwrites it with the bf16 w tile (alias).
    if (lane < 16) {
        const int row = 16*wid + lane;
        float wv[64];
        const float4* brow = reinterpret_cast<const float4*>(stage + row * 68);
        const float4* bvp  = reinterpret_cast<const float4*>(sbv);
        #pragma unroll
        for (int g = 0; g < 16; g++) {
            const float4 b = brow[g], v = bvp[g];
            wv[4*g+0] = b.x + v.x; wv[4*g+1] = b.y + v.y;
            wv[4*g+2] = b.z + v.z; wv[4*g+3] = b.w + v.w;
        }
        wv[0] = fmaxf(wv[0], 0.0f);
        #pragma unroll
        for (int i = 1; i < 64; i++) {
            const float4* drow = sD11p4 + d11_off4(i);   // compile-time offset
            float a0 = wv[i], a1 = 0.0f, a2 = 0.0f, a3 = 0.0f;
            const int ng = (i >> 2) + 1;
            #pragma unroll
            for (int g = 0; g < 16; g++) {
                if (g >= ng) break;                      // strict-lower zeros pad tail
                const float4 d = drow[g];
                a0 = fmaf(d.x, wv[4*g+0], a0);
                a1 = fmaf(d.y, wv[4*g+1], a1);
                a2 = fmaf(d.z, wv[4*g+2], a2);
                a3 = fmaf(d.w, wv[4*g+3], a3);
            }
            wv[i] = fmaxf((a0 + a1) + (a2 + a3), 0.0f);
        }
        char* wt = smem + OFF_S + row * SW;              // overwrite own stage row
        #pragma unroll
        for (int b8 = 0; b8 < 8; b8++) {
            unsigned hp[4], lp[4];
            #pragma unroll
            for (int t = 0; t < 4; t++)
                split2(wv[8*b8 + 2*t], wv[8*b8 + 2*t + 1], hp[t], lp[t]);
            *reinterpret_cast<uint4*>(wt + 16*b8)       = make_uint4(hp[0], hp[1], hp[2], hp[3]);
            *reinterpret_cast<uint4*>(wt + 128 + 16*b8) = make_uint4(lp[0], lp[1], lp[2], lp[3]);
        }
    }
    __syncwarp();

    // ===== GEMM2: out = [act] x W2a^T + [w] x B1^T =====
    {
        float acc[8][4] = {};
        #pragma unroll
        for (int c = 0; c < 5; c++) {
            unsigned ah[4], al[4];
            ldsm4(ah, a_act + 32 * c);
            gemm_b8(acc, b_w2a, SA, c,     ah);
            gemm_b8(acc, b_w2a, SA, 5 + c, ah);
            ldsm4(al, a_act + 32 * (5 + c));
            gemm_b8(acc, b_w2a, SA, c,     al);
        }
        #pragma unroll
        for (int c = 0; c < 4; c++) {
            unsigned ah[4], al[4];
            ldsm4(ah, a_wt + 32 * c);
            gemm_b8(acc, b_w2b, SW, c,     ah);
            gemm_b8(acc, b_w2b, SW, 4 + c, ah);
            ldsm4(al, a_wt + 32 * (4 + c));
            gemm_b8(acc, b_w2b, SW, c,     al);
        }
        __syncwarp();   // all wt fragment loads done before stage overwrite
        #pragma unroll
        for (int n = 0; n < 8; n++) {
            const int c0 = 8*n + 2*q;
            const float2 bx2 = *reinterpret_cast<const float2*>(sbx + c0);
            *reinterpret_cast<float2*>(stage + (16*wid + rh    ) * 68 + c0) =
                make_float2(acc[n][0] + bx2.x, acc[n][1] + bx2.y);
            *reinterpret_cast<float2*>(stage + (16*wid + rh + 8) * 68 + c0) =
                make_float2(acc[n][2] + bx2.x, acc[n][3] + bx2.y);
        }
    }
    __syncwarp();

    // ---------- store own 16 rows ----------
    float4* gout4 = reinterpret_cast<float4*>(gout);
    #pragma unroll
    for (int i = 0; i < 8; i++) {
        const int idx = i * 32 + lane;
        const int row = 16*wid + (idx >> 4), c = idx & 15;
        if (rowbase + row < N)
            gout4[(size_t)(rowbase + row) * 16 + c] =
                *reinterpret_cast<float4*>(stage + row * 68 + 4*c);
    }
}

extern "C" void kernel_launch(void* const* d_in, const int* in_sizes, int n_in,
                              void* d_out, int out_size) {
    (void)n_in; (void)out_size;
    const float* x   = (const float*)d_in[0];
    const float* u   = (const float*)d_in[1];
    const float* A   = (const float*)d_in[2];
    const float* B1  = (const float*)d_in[3];
    const float* B2  = (const float*)d_in[4];
    const float* C1  = (const float*)d_in[5];
    const float* D11 = (const float*)d_in[6];
    const float* D12 = (const float*)d_in[7];
    const float* bv  = (const float*)d_in[8];
    const float* bx  = (const float*)d_in[9];
    float* out = (float*)d_out;

    const int N = in_sizes[0] / 64;                     // 262144
    const int grid = (N + MROWS - 1) / MROWS;           // 1024

    renl2_prep_kernel<<<1, 256>>>(A, B1, B2, C1, D12);

    cudaFuncSetAttribute(renl2_hmma_kernel,
                         cudaFuncAttributeMaxDynamicSharedMemorySize,
                         SMEM_BYTES);
    renl2_hmma_kernel<<<grid, NTHREADS, SMEM_BYTES>>>(
        x, u, D11, bv, bx, out, N);
}

// round 11
// speedup vs baseline: 2.5721x; 1.1969x over previous
#include <cuda_runtime.h>
#include <cuda_bf16.h>
#include <cstdint>

#define NTHREADS 512
#define MROWS    256
#define SA 336            // act / W1 / W2a row stride in BYTES (168 bf16)
#define SW 272            // stage(f32x68) / wt / W2B / D11B row stride in BYTES

// ---------------- SMEM byte layout (229.6 KB, 1 CTA/SM, 16 warps) ----------------
#define OFF_W1    0        // bf16 [64 x 168]: C1_hi D12_hi | C1_lo D12_lo
#define OFF_W2A   21504    // bf16 [64 x 168]: A_hi  B2_hi  | A_lo  B2_lo
#define OFF_W2B   43008    // bf16 [64 x 136]: B1_hi | B1_lo
#define OFF_D11B  60416    // bf16 [48 x 136]: D11 rows 16..63, hi | lo  (13056 B)
#define OFF_BV    73472    // f32 [64]
#define OFF_BX    73728    // f32 [64]
#define OFF_ACT   73984    // bf16 [256 x 168]: x_hi | u_hi | x_lo | u_lo (86016 B)
#define OFF_S     160000   // ALIASED: stage f32[256 x 68] / wt bf16 [hi_b|lo_b] at byte 64b
#define SMEM_BYTES 229632

// pre-split weight tiles in global scratch (written by prep kernel)
__device__ __align__(16) unsigned char gW1s  [21504];
__device__ __align__(16) unsigned char gW2As [21504];
__device__ __align__(16) unsigned char gW2Bs [17408];
__device__ __align__(16) unsigned char gD11Bs[13056];

__device__ __forceinline__ uint32_t smem_u32(const void* p) {
    uint32_t a;
    asm("{ .reg .u64 t; cvta.to.shared.u64 t, %1; cvt.u32.u64 %0, t; }" : "=r"(a) : "l"(p));
    return a;
}
__device__ __forceinline__ void ldsm4(unsigned r[4], uint32_t addr) {
    asm volatile("ldmatrix.sync.aligned.m8n8.x4.shared.b16 {%0,%1,%2,%3}, [%4];"
        : "=r"(r[0]), "=r"(r[1]), "=r"(r[2]), "=r"(r[3]) : "r"(addr));
}
__device__ __forceinline__ void mma16816(float d[4], const unsigned a[4], unsigned b0, unsigned b1) {
    asm volatile("mma.sync.aligned.m16n8k16.row.col.f32.bf16.bf16.f32 "
        "{%0,%1,%2,%3},{%4,%5,%6,%7},{%8,%9},{%0,%1,%2,%3};"
        : "+f"(d[0]), "+f"(d[1]), "+f"(d[2]), "+f"(d[3])
        : "r"(a[0]), "r"(a[1]), "r"(a[2]), "r"(a[3]), "r"(b0), "r"(b1));
}
__device__ __forceinline__ void split2(float a, float b, unsigned& hi, unsigned& lo) {
    const __nv_bfloat16 ha = __float2bfloat16_rn(a), hb = __float2bfloat16_rn(b);
    hi = (unsigned)(*reinterpret_cast<const unsigned short*>(&ha))
       | ((unsigned)(*reinterpret_cast<const unsigned short*>(&hb)) << 16);
    const __nv_bfloat162 t = __floats2bfloat162_rn(a - __bfloat162float(ha),
                                                   b - __bfloat162float(hb));
    lo = *reinterpret_cast<const unsigned*>(&t);
}
__device__ __forceinline__ void gemm_b8(float (*acc)[4], uint32_t blane, int strideB,
                                        int cb, const unsigned a[4]) {
    #pragma unroll
    for (int p = 0; p < 4; p++) {
        unsigned bf[4];
        ldsm4(bf, blane + p * 16 * strideB + 32 * cb);
        mma16816(acc[2*p + 0], a, bf[0], bf[2]);
        mma16816(acc[2*p + 1], a, bf[1], bf[3]);
    }
}

// ---------------- prep kernel: split weights once ----------------
__global__ void __launch_bounds__(256)
renl2_prep_kernel(const float* __restrict__ gA,  const float* __restrict__ gB1,
                  const float* __restrict__ gB2, const float* __restrict__ gC1,
                  const float* __restrict__ gD11,const float* __restrict__ gD12)
{
    const int tid = threadIdx.x;
    #pragma unroll 1
    for (int idx = tid; idx < 64 * 40; idx += 256) {
        const int n = idx / 40, k = (idx - n * 40) * 2;
        float v1a, v1b, v2a, v2b;
        if (k < 64) { v1a = gC1[n*64 + k]; v1b = gC1[n*64 + k + 1];
                      v2a = gA [n*64 + k]; v2b = gA [n*64 + k + 1]; }
        else        { v1a = gD12[n*16 + k - 64]; v1b = gD12[n*16 + k - 63];
                      v2a = gB2 [n*16 + k - 64]; v2b = gB2 [n*16 + k - 63]; }
        unsigned h1, l1, h2, l2;
        split2(v1a, v1b, h1, l1);
        split2(v2a, v2b, h2, l2);
        *reinterpret_cast<unsigned*>(gW1s  + n*SA + 2*k)       = h1;
        *reinterpret_cast<unsigned*>(gW1s  + n*SA + 160 + 2*k) = l1;
        *reinterpret_cast<unsigned*>(gW2As + n*SA + 2*k)       = h2;
        *reinterpret_cast<unsigned*>(gW2As + n*SA + 160 + 2*k) = l2;
    }
    #pragma unroll 1
    for (int idx = tid; idx < 64 * 32; idx += 256) {
        const int n = idx >> 5, k = (idx & 31) * 2;
        unsigned h, l;
        split2(gB1[n*64 + k], gB1[n*64 + k + 1], h, l);
        *reinterpret_cast<unsigned*>(gW2Bs + n*SW + 2*k)       = h;
        *reinterpret_cast<unsigned*>(gW2Bs + n*SW + 128 + 2*k) = l;
    }
    #pragma unroll 1
    for (int idx = tid; idx < 48 * 32; idx += 256) {   // D11 rows 16..63
        const int nl = idx >> 5, k = (idx & 31) * 2, n = nl + 16;
        unsigned h, l;
        split2(gD11[n*64 + k], gD11[n*64 + k + 1], h, l);
        *reinterpret_cast<unsigned*>(gD11Bs + nl*SW + 2*k)       = h;
        *reinterpret_cast<unsigned*>(gD11Bs + nl*SW + 128 + 2*k) = l;
    }
}

// ---------------- main kernel ----------------
__global__ void __launch_bounds__(NTHREADS, 1)
renl2_hmma_kernel(const float* __restrict__ gx,  const float* __restrict__ gu,
                  const float* __restrict__ gD11,
                  const float* __restrict__ gbv, const float* __restrict__ gbx,
                  float* __restrict__ gout, int N)
{
    extern __shared__ char smem[];
    const uint32_t sbase = smem_u32(smem);
    const int tid  = threadIdx.x;
    const int lane = tid & 31;
    const int wid  = tid >> 5;
    const int rowbase = blockIdx.x * MROWS;

    float* stage = reinterpret_cast<float*>(smem + OFF_S);    // aliased with wt
    float* sbv   = reinterpret_cast<float*>(smem + OFF_BV);
    float* sbx   = reinterpret_cast<float*>(smem + OFF_BX);

    // ---------- copy pre-split weights + biases ----------
    {
        const uint4* s1 = reinterpret_cast<const uint4*>(gW1s);
        const uint4* s2 = reinterpret_cast<const uint4*>(gW2As);
        uint4* d1 = reinterpret_cast<uint4*>(smem + OFF_W1);
        uint4* d2 = reinterpret_cast<uint4*>(smem + OFF_W2A);
        #pragma unroll 1
        for (int i = tid; i < 21504/16; i += NTHREADS) { d1[i] = s1[i]; d2[i] = s2[i]; }
        const uint4* s3 = reinterpret_cast<const uint4*>(gW2Bs);
        uint4* d3 = reinterpret_cast<uint4*>(smem + OFF_W2B);
        #pragma unroll 1
        for (int i = tid; i < 17408/16; i += NTHREADS) d3[i] = s3[i];
        const uint4* s4 = reinterpret_cast<const uint4*>(gD11Bs);
        uint4* d4 = reinterpret_cast<uint4*>(smem + OFF_D11B);
        #pragma unroll 1
        for (int i = tid; i < 13056/16; i += NTHREADS) d4[i] = s4[i];
        if (tid >= 64 && tid < 128)  sbv[tid - 64]  = gbv[tid - 64];
        if (tid >= 128 && tid < 192) sbx[tid - 128] = gbx[tid - 128];
    }

    // ---------- stage activations (hi/lo split) ----------
    const float4* gx4 = reinterpret_cast<const float4*>(gx);
    #pragma unroll 1
    for (int idx = tid; idx < MROWS * 16; idx += NTHREADS) {
        const int row = idx >> 4, q0 = idx & 15;
        if (rowbase + row >= N) continue;
        const float4 v = gx4[(size_t)(rowbase + row) * 16 + q0];
        unsigned h0, l0, h1, l1;
        split2(v.x, v.y, h0, l0);
        split2(v.z, v.w, h1, l1);
        char* rp = smem + OFF_ACT + row * SA;
        *reinterpret_cast<unsigned*>(rp + 8*q0)           = h0;
        *reinterpret_cast<unsigned*>(rp + 8*q0 + 4)       = h1;
        *reinterpret_cast<unsigned*>(rp + 160 + 8*q0)     = l0;
        *reinterpret_cast<unsigned*>(rp + 160 + 8*q0 + 4) = l1;
    }
    const float4* gu4 = reinterpret_cast<const float4*>(gu);
    #pragma unroll 1
    for (int idx = tid; idx < MROWS * 4; idx += NTHREADS) {
        const int row = idx >> 2, q0 = idx & 3;
        if (rowbase + row >= N) continue;
        const float4 v = gu4[(size_t)(rowbase + row) * 4 + q0];
        unsigned h0, l0, h1, l1;
        split2(v.x, v.y, h0, l0);
        split2(v.z, v.w, h1, l1);
        char* rp = smem + OFF_ACT + row * SA;
        *reinterpret_cast<unsigned*>(rp + 128 + 8*q0)     = h0;
        *reinterpret_cast<unsigned*>(rp + 128 + 8*q0 + 4) = h1;
        *reinterpret_cast<unsigned*>(rp + 288 + 8*q0)     = l0;
        *reinterpret_cast<unsigned*>(rp + 288 + 8*q0 + 4) = l1;
    }
    __syncthreads();   // ONLY block-wide barrier

    // ---------- per-warp pipeline (warp owns rows 16*wid..+15) ----------
    const uint32_t a_act  = sbase + OFF_ACT  + (16*wid + (lane & 15)) * SA + 16 * (lane >> 4);
    const uint32_t a_wt   = sbase + OFF_S    + (16*wid + (lane & 15)) * SW + 16 * (lane >> 4);
    const uint32_t b_w1   = sbase + OFF_W1   + (lane & 15) * SA + 16 * (lane >> 4);
    const uint32_t b_w2a  = sbase + OFF_W2A  + (lane & 15) * SA + 16 * (lane >> 4);
    const uint32_t b_w2b  = sbase + OFF_W2B  + (lane & 15) * SW + 16 * (lane >> 4);
    const uint32_t b_d11  = sbase + OFF_D11B + (lane & 15) * SW + 16 * (lane >> 4);

    const int q  = lane & 3;
    const int rh = lane >> 2;

    // ===== GEMM1: base = [act] x W1^T ; keep acc live, spill only tiles 0,1 =====
    float acc[8][4] = {};
    #pragma unroll
    for (int c = 0; c < 5; c++) {
        unsigned ah[4], al[4];
        ldsm4(ah, a_act + 32 * c);
        gemm_b8(acc, b_w1, SA, c,     ah);      // hi . hi
        gemm_b8(acc, b_w1, SA, 5 + c, ah);      // hi . lo
        ldsm4(al, a_act + 32 * (5 + c));
        gemm_b8(acc, b_w1, SA, c,     al);      // lo . hi
    }
    #pragma unroll
    for (int n = 0; n < 2; n++) {               // only block-0 cols to stage
        const int c0 = 8*n + 2*q;
        *reinterpret_cast<float2*>(stage + (16*wid + rh    ) * 68 + c0) = make_float2(acc[n][0], acc[n][1]);
        *reinterpret_cast<float2*>(stage + (16*wid + rh + 8) * 68 + c0) = make_float2(acc[n][2], acc[n][3]);
    }
    __syncwarp();

    // ===== blocked triangular solve with ReLU =====
    #pragma unroll
    for (int b = 0; b < 4; b++) {
        // --- diagonal 16x16 serial solve (lanes 0-15, one sample each) ---
        if (lane < 16) {
            const int row = 16*wid + lane;
            float wv[16];
            const float4* srow = reinterpret_cast<const float4*>(stage + row * 68 + 16*b);
            const float4* bvp  = reinterpret_cast<const float4*>(sbv + 16*b);
            #pragma unroll
            for (int g = 0; g < 4; g++) {
                const float4 s = srow[g], v = bvp[g];
                wv[4*g+0] = s.x + v.x; wv[4*g+1] = s.y + v.y;
                wv[4*g+2] = s.z + v.z; wv[4*g+3] = s.w + v.w;
            }
            wv[0] = fmaxf(wv[0], 0.0f);
            #pragma unroll
            for (int il = 1; il < 16; il++) {
                // D11 row (16b+il), cols 16b.. : strict-lower zeros pad the tail
                const float4* dptr = reinterpret_cast<const float4*>(gD11 + (16*b + il) * 64 + 16*b);
                float a0 = wv[il], a1 = 0.0f, a2 = 0.0f, a3 = 0.0f;
                const int ng = (il + 3) >> 2;
                #pragma unroll
                for (int g = 0; g < 4; g++) {
                    if (g >= ng) break;
                    const float4 d = dptr[g];
                    a0 = fmaf(d.x, wv[4*g+0], a0);
                    a1 = fmaf(d.y, wv[4*g+1], a1);
                    a2 = fmaf(d.z, wv[4*g+2], a2);
                    a3 = fmaf(d.w, wv[4*g+3], a3);
                }
                wv[il] = fmaxf((a0 + a1) + (a2 + a3), 0.0f);
            }
            // write w_b as bf16 [hi_b | lo_b] over the stage bytes just consumed
            char* wtp = smem + OFF_S + row * SW + 64*b;
            unsigned hp[8], lp[8];
            #pragma unroll
            for (int t = 0; t < 8; t++) split2(wv[2*t], wv[2*t+1], hp[t], lp[t]);
            *reinterpret_cast<uint4*>(wtp)      = make_uint4(hp[0], hp[1], hp[2], hp[3]);
            *reinterpret_cast<uint4*>(wtp + 16) = make_uint4(hp[4], hp[5], hp[6], hp[7]);
            *reinterpret_cast<uint4*>(wtp + 32) = make_uint4(lp[0], lp[1], lp[2], lp[3]);
            *reinterpret_cast<uint4*>(wtp + 48) = make_uint4(lp[4], lp[5], lp[6], lp[7]);
        }
        __syncwarp();

        // --- HMMA update of remaining cols, then spill next block to stage ---
        if (b < 3) {
            unsigned ahi[4], alo[4];
            ldsm4(ahi, a_wt + 64*b);
            ldsm4(alo, a_wt + 64*b + 32);
            #pragma unroll
            for (int p = 1; p < 4; p++) {
                if (p <= b) continue;             // compile-time trimmed
                unsigned bh[4], bl[4];
                const uint32_t bb = b_d11 + (p - 1) * 16 * SW;
                ldsm4(bh, bb + 32*b);
                ldsm4(bl, bb + 128 + 32*b);
                mma16816(acc[2*p    ], ahi, bh[0], bh[2]);
                mma16816(acc[2*p + 1], ahi, bh[1], bh[3]);
                mma16816(acc[2*p    ], alo, bh[0], bh[2]);
                mma16816(acc[2*p + 1], alo, bh[1], bh[3]);
                mma16816(acc[2*p    ], ahi, bl[0], bl[2]);
                mma16816(acc[2*p + 1], ahi, bl[1], bl[3]);
            }
            #pragma unroll
            for (int n = 2*(b+1); n <= 2*(b+1) + 1; n++) {
                const int c0 = 8*n + 2*q;
                *reinterpret_cast<float2*>(stage + (16*wid + rh    ) * 68 + c0) = make_float2(acc[n][0], acc[n][1]);
                *reinterpret_cast<float2*>(stage + (16*wid + rh + 8) * 68 + c0) = make_float2(acc[n][2], acc[n][3]);
            }
            __syncwarp();
        }
    }
    __syncwarp();

    // ===== GEMM2: out = [act] x W2a^T + [w] x B1^T =====
    {
        float acc2[8][4] = {};
        #pragma unroll
        for (int c = 0; c < 5; c++) {
            unsigned ah[4], al[4];
            ldsm4(ah, a_act + 32 * c);
            gemm_b8(acc2, b_w2a, SA, c,     ah);
            gemm_b8(acc2, b_w2a, SA, 5 + c, ah);
            ldsm4(al, a_act + 32 * (5 + c));
            gemm_b8(acc2, b_w2a, SA, c,     al);
        }
        #pragma unroll
        for (int c = 0; c < 4; c++) {
            unsigned ah[4], al[4];
            ldsm4(ah, a_wt + 64*c);             // w hi chunk c (interleaved layout)
            gemm_b8(acc2, b_w2b, SW, c,     ah);
            gemm_b8(acc2, b_w2b, SW, 4 + c, ah);
            ldsm4(al, a_wt + 64*c + 32);        // w lo chunk c
            gemm_b8(acc2, b_w2b, SW, c,     al);
        }
        __syncwarp();   // all wt fragment loads done before stage overwrite
        #pragma unroll
        for (int n = 0; n < 8; n++) {
            const int c0 = 8*n + 2*q;
            const float2 bx2 = *reinterpret_cast<const float2*>(sbx + c0);
            *reinterpret_cast<float2*>(stage + (16*wid + rh    ) * 68 + c0) =
                make_float2(acc2[n][0] + bx2.x, acc2[n][1] + bx2.y);
            *reinterpret_cast<float2*>(stage + (16*wid + rh + 8) * 68 + c0) =
                make_float2(acc2[n][2] + bx2.x, acc2[n][3] + bx2.y);
        }
    }
    __syncwarp();

    // ---------- store own 16 rows ----------
    float4* gout4 = reinterpret_cast<float4*>(gout);
    #pragma unroll
    for (int i = 0; i < 8; i++) {
        const int idx = i * 32 + lane;
        const int row = 16*wid + (idx >> 4), c = idx & 15;
        if (rowbase + row < N)
            gout4[(size_t)(rowbase + row) * 16 + c] =
                *reinterpret_cast<float4*>(stage + row * 68 + 4*c);
    }
}

extern "C" void kernel_launch(void* const* d_in, const int* in_sizes, int n_in,
                              void* d_out, int out_size) {
    (void)n_in; (void)out_size;
    const float* x   = (const float*)d_in[0];
    const float* u   = (const float*)d_in[1];
    const float* A   = (const float*)d_in[2];
    const float* B1  = (const float*)d_in[3];
    const float* B2  = (const float*)d_in[4];
    const float* C1  = (const float*)d_in[5];
    const float* D11 = (const float*)d_in[6];
    const float* D12 = (const float*)d_in[7];
    const float* bv  = (const float*)d_in[8];
    const float* bx  = (const float*)d_in[9];
    float* out = (float*)d_out;

    const int N = in_sizes[0] / 64;                     // 262144
    const int grid = (N + MROWS - 1) / MROWS;           // 1024

    renl2_prep_kernel<<<1, 256>>>(A, B1, B2, C1, D11, D12);

    cudaFuncSetAttribute(renl2_hmma_kernel,
                         cudaFuncAttributeMaxDynamicSharedMemorySize,
                         SMEM_BYTES);
    renl2_hmma_kernel<<<grid, NTHREADS, SMEM_BYTES>>>(
        x, u, D11, bv, bx, out, N);
}

// round 12
// speedup vs baseline: 2.6562x; 1.0327x over previous
#include <cuda_runtime.h>
#include <cuda_bf16.h>
#include <cstdint>

#define NTHREADS 512
#define MROWS    256
#define SA 336            // act / W1 / W2a row stride in BYTES (168 bf16)
#define SW 272            // stage(f32x68) / wt / W2B / D11B row stride in BYTES

// ---------------- SMEM byte layout (224 KB, 1 CTA/SM, 16 warps) ----------------
#define OFF_W1    0        // bf16 [64 x 168]: C1_hi D12_hi | C1_lo D12_lo
#define OFF_W2A   21504    // bf16 [64 x 168]: A_hi  B2_hi  | A_lo  B2_lo
#define OFF_W2B   43008    // bf16 [64 x 136]: B1_hi | B1_lo
#define OFF_D11B  60416    // bf16 [48 x 136]: D11 rows 16..63, hi | lo  (13056 B)
#define OFF_BV    73472    // f32 [64]
#define OFF_BX    73728    // f32 [64]
#define OFF_ACT   73984    // bf16 [256 x 168]: x_hi | u_hi | x_lo | u_lo (86016 B)
#define OFF_S     160000   // ALIASED: stage f32[256 x 68] / wt bf16 [hi_b|lo_b] at byte 64b
#define SMEM_BYTES 229632

// pre-split weight tiles in global scratch (written by prep kernel)
__device__ __align__(16) unsigned char gW1s  [21504];
__device__ __align__(16) unsigned char gW2As [21504];
__device__ __align__(16) unsigned char gW2Bs [17408];
__device__ __align__(16) unsigned char gD11Bs[13056];

__device__ __forceinline__ uint32_t smem_u32(const void* p) {
    uint32_t a;
    asm("{ .reg .u64 t; cvta.to.shared.u64 t, %1; cvt.u32.u64 %0, t; }" : "=r"(a) : "l"(p));
    return a;
}
__device__ __forceinline__ void ldsm4(unsigned r[4], uint32_t addr) {
    asm volatile("ldmatrix.sync.aligned.m8n8.x4.shared.b16 {%0,%1,%2,%3}, [%4];"
        : "=r"(r[0]), "=r"(r[1]), "=r"(r[2]), "=r"(r[3]) : "r"(addr));
}
__device__ __forceinline__ void mma16816(float d[4], const unsigned a[4], unsigned b0, unsigned b1) {
    asm volatile("mma.sync.aligned.m16n8k16.row.col.f32.bf16.bf16.f32 "
        "{%0,%1,%2,%3},{%4,%5,%6,%7},{%8,%9},{%0,%1,%2,%3};"
        : "+f"(d[0]), "+f"(d[1]), "+f"(d[2]), "+f"(d[3])
        : "r"(a[0]), "r"(a[1]), "r"(a[2]), "r"(a[3]), "r"(b0), "r"(b1));
}
__device__ __forceinline__ void split2(float a, float b, unsigned& hi, unsigned& lo) {
    const __nv_bfloat16 ha = __float2bfloat16_rn(a), hb = __float2bfloat16_rn(b);
    hi = (unsigned)(*reinterpret_cast<const unsigned short*>(&ha))
       | ((unsigned)(*reinterpret_cast<const unsigned short*>(&hb)) << 16);
    const __nv_bfloat162 t = __floats2bfloat162_rn(a - __bfloat162float(ha),
                                                   b - __bfloat162float(hb));
    lo = *reinterpret_cast<const unsigned*>(&t);
}
__device__ __forceinline__ void gemm_b8(float (*acc)[4], uint32_t blane, int strideB,
                                        int cb, const unsigned a[4]) {
    #pragma unroll
    for (int p = 0; p < 4; p++) {
        unsigned bf[4];
        ldsm4(bf, blane + p * 16 * strideB + 32 * cb);
        mma16816(acc[2*p + 0], a, bf[0], bf[2]);
        mma16816(acc[2*p + 1], a, bf[1], bf[3]);
    }
}

// ---------------- prep kernel: split weights once (8 CTAs) ----------------
__global__ void __launch_bounds__(128)
renl2_prep_kernel(const float* __restrict__ gA,  const float* __restrict__ gB1,
                  const float* __restrict__ gB2, const float* __restrict__ gC1,
                  const float* __restrict__ gD11,const float* __restrict__ gD12)
{
    const int tid = blockIdx.x * 128 + threadIdx.x;   // 0..1023
    #pragma unroll 1
    for (int idx = tid; idx < 64 * 40; idx += 1024) {
        const int n = idx / 40, k = (idx - n * 40) * 2;
        float v1a, v1b, v2a, v2b;
        if (k < 64) { v1a = gC1[n*64 + k]; v1b = gC1[n*64 + k + 1];
                      v2a = gA [n*64 + k]; v2b = gA [n*64 + k + 1]; }
        else        { v1a = gD12[n*16 + k - 64]; v1b = gD12[n*16 + k - 63];
                      v2a = gB2 [n*16 + k - 64]; v2b = gB2 [n*16 + k - 63]; }
        unsigned h1, l1, h2, l2;
        split2(v1a, v1b, h1, l1);
        split2(v2a, v2b, h2, l2);
        *reinterpret_cast<unsigned*>(gW1s  + n*SA + 2*k)       = h1;
        *reinterpret_cast<unsigned*>(gW1s  + n*SA + 160 + 2*k) = l1;
        *reinterpret_cast<unsigned*>(gW2As + n*SA + 2*k)       = h2;
        *reinterpret_cast<unsigned*>(gW2As + n*SA + 160 + 2*k) = l2;
    }
    #pragma unroll 1
    for (int idx = tid; idx < 64 * 32; idx += 1024) {
        const int n = idx >> 5, k = (idx & 31) * 2;
        unsigned h, l;
        split2(gB1[n*64 + k], gB1[n*64 + k + 1], h, l);
        *reinterpret_cast<unsigned*>(gW2Bs + n*SW + 2*k)       = h;
        *reinterpret_cast<unsigned*>(gW2Bs + n*SW + 128 + 2*k) = l;
    }
    #pragma unroll 1
    for (int idx = tid; idx < 48 * 32; idx += 1024) {   // D11 rows 16..63
        const int nl = idx >> 5, k = (idx & 31) * 2, n = nl + 16;
        unsigned h, l;
        split2(gD11[n*64 + k], gD11[n*64 + k + 1], h, l);
        *reinterpret_cast<unsigned*>(gD11Bs + nl*SW + 2*k)       = h;
        *reinterpret_cast<unsigned*>(gD11Bs + nl*SW + 128 + 2*k) = l;
    }
}

// ---------------- main kernel ----------------
__global__ void __launch_bounds__(NTHREADS, 1)
renl2_hmma_kernel(const float* __restrict__ gx,  const float* __restrict__ gu,
                  const float* __restrict__ gD11,
                  const float* __restrict__ gbv, const float* __restrict__ gbx,
                  float* __restrict__ gout, int N)
{
    extern __shared__ char smem[];
    const uint32_t sbase = smem_u32(smem);
    const int tid  = threadIdx.x;
    const int lane = tid & 31;
    const int wid  = tid >> 5;
    const int rowbase = blockIdx.x * MROWS;

    float* stage = reinterpret_cast<float*>(smem + OFF_S);    // aliased with wt
    float* sbv   = reinterpret_cast<float*>(smem + OFF_BV);
    float* sbx   = reinterpret_cast<float*>(smem + OFF_BX);

    // ---------- copy pre-split weights + biases ----------
    {
        const uint4* s1 = reinterpret_cast<const uint4*>(gW1s);
        const uint4* s2 = reinterpret_cast<const uint4*>(gW2As);
        uint4* d1 = reinterpret_cast<uint4*>(smem + OFF_W1);
        uint4* d2 = reinterpret_cast<uint4*>(smem + OFF_W2A);
        #pragma unroll 1
        for (int i = tid; i < 21504/16; i += NTHREADS) { d1[i] = s1[i]; d2[i] = s2[i]; }
        const uint4* s3 = reinterpret_cast<const uint4*>(gW2Bs);
        uint4* d3 = reinterpret_cast<uint4*>(smem + OFF_W2B);
        #pragma unroll 1
        for (int i = tid; i < 17408/16; i += NTHREADS) d3[i] = s3[i];
        const uint4* s4 = reinterpret_cast<const uint4*>(gD11Bs);
        uint4* d4 = reinterpret_cast<uint4*>(smem + OFF_D11B);
        #pragma unroll 1
        for (int i = tid; i < 13056/16; i += NTHREADS) d4[i] = s4[i];
        if (tid >= 64 && tid < 128)  sbv[tid - 64]  = gbv[tid - 64];
        if (tid >= 128 && tid < 192) sbx[tid - 128] = gbx[tid - 128];
    }

    // ---------- stage activations (hi/lo split, uint2 stores) ----------
    const float4* gx4 = reinterpret_cast<const float4*>(gx);
    #pragma unroll 1
    for (int idx = tid; idx < MROWS * 16; idx += NTHREADS) {
        const int row = idx >> 4, q0 = idx & 15;
        if (rowbase + row >= N) continue;
        const float4 v = gx4[(size_t)(rowbase + row) * 16 + q0];
        unsigned h0, l0, h1, l1;
        split2(v.x, v.y, h0, l0);
        split2(v.z, v.w, h1, l1);
        char* rp = smem + OFF_ACT + row * SA;
        *reinterpret_cast<uint2*>(rp + 8*q0)       = make_uint2(h0, h1);
        *reinterpret_cast<uint2*>(rp + 160 + 8*q0) = make_uint2(l0, l1);
    }
    const float4* gu4 = reinterpret_cast<const float4*>(gu);
    #pragma unroll 1
    for (int idx = tid; idx < MROWS * 4; idx += NTHREADS) {
        const int row = idx >> 2, q0 = idx & 3;
        if (rowbase + row >= N) continue;
        const float4 v = gu4[(size_t)(rowbase + row) * 4 + q0];
        unsigned h0, l0, h1, l1;
        split2(v.x, v.y, h0, l0);
        split2(v.z, v.w, h1, l1);
        char* rp = smem + OFF_ACT + row * SA;
        *reinterpret_cast<uint2*>(rp + 128 + 8*q0) = make_uint2(h0, h1);
        *reinterpret_cast<uint2*>(rp + 288 + 8*q0) = make_uint2(l0, l1);
    }
    __syncthreads();   // ONLY block-wide barrier

    // ---------- per-warp pipeline (warp owns rows 16*wid..+15) ----------
    const uint32_t a_act  = sbase + OFF_ACT  + (16*wid + (lane & 15)) * SA + 16 * (lane >> 4);
    const uint32_t a_wt   = sbase + OFF_S    + (16*wid + (lane & 15)) * SW + 16 * (lane >> 4);
    const uint32_t b_w1   = sbase + OFF_W1   + (lane & 15) * SA + 16 * (lane >> 4);
    const uint32_t b_w2a  = sbase + OFF_W2A  + (lane & 15) * SA + 16 * (lane >> 4);
    const uint32_t b_w2b  = sbase + OFF_W2B  + (lane & 15) * SW + 16 * (lane >> 4);
    const uint32_t b_d11  = sbase + OFF_D11B + (lane & 15) * SW + 16 * (lane >> 4);

    const int q  = lane & 3;
    const int rh = lane >> 2;

    // ===== merged GEMM1 + GEMM2a: one pass over act fragments =====
    //   acc  = [act] x W1^T   (w pre-activation)
    //   acc2 = [act] x W2a^T  (out partial, independent of w)
    float acc[8][4] = {};
    float acc2[8][4] = {};
    #pragma unroll
    for (int c = 0; c < 5; c++) {
        unsigned ah[4], al[4];
        ldsm4(ah, a_act + 32 * c);
        gemm_b8(acc,  b_w1,  SA, c,     ah);    // hi . hi
        gemm_b8(acc,  b_w1,  SA, 5 + c, ah);    // hi . lo
        gemm_b8(acc2, b_w2a, SA, c,     ah);
        gemm_b8(acc2, b_w2a, SA, 5 + c, ah);
        ldsm4(al, a_act + 32 * (5 + c));
        gemm_b8(acc,  b_w1,  SA, c,     al);    // lo . hi
        gemm_b8(acc2, b_w2a, SA, c,     al);
    }
    #pragma unroll
    for (int n = 0; n < 2; n++) {               // only block-0 cols to stage
        const int c0 = 8*n + 2*q;
        *reinterpret_cast<float2*>(stage + (16*wid + rh    ) * 68 + c0) = make_float2(acc[n][0], acc[n][1]);
        *reinterpret_cast<float2*>(stage + (16*wid + rh + 8) * 68 + c0) = make_float2(acc[n][2], acc[n][3]);
    }
    __syncwarp();

    // ===== blocked triangular solve with ReLU =====
    #pragma unroll
    for (int b = 0; b < 4; b++) {
        // --- diagonal 16x16 serial solve (lanes 0-15, one sample each) ---
        if (lane < 16) {
            const int row = 16*wid + lane;
            float wv[16];
            const float4* srow = reinterpret_cast<const float4*>(stage + row * 68 + 16*b);
            const float4* bvp  = reinterpret_cast<const float4*>(sbv + 16*b);
            #pragma unroll
            for (int g = 0; g < 4; g++) {
                const float4 s = srow[g], v = bvp[g];
                wv[4*g+0] = s.x + v.x; wv[4*g+1] = s.y + v.y;
                wv[4*g+2] = s.z + v.z; wv[4*g+3] = s.w + v.w;
            }
            wv[0] = fmaxf(wv[0], 0.0f);
            #pragma unroll
            for (int il = 1; il < 16; il++) {
                const float4* dptr = reinterpret_cast<const float4*>(gD11 + (16*b + il) * 64 + 16*b);
                float a0 = wv[il], a1 = 0.0f, a2 = 0.0f, a3 = 0.0f;
                const int ng = (il + 3) >> 2;
                #pragma unroll
                for (int g = 0; g < 4; g++) {
                    if (g >= ng) break;                  // strict-lower zeros pad tail
                    const float4 d = dptr[g];
                    a0 = fmaf(d.x, wv[4*g+0], a0);
                    a1 = fmaf(d.y, wv[4*g+1], a1);
                    a2 = fmaf(d.z, wv[4*g+2], a2);
                    a3 = fmaf(d.w, wv[4*g+3], a3);
                }
                wv[il] = fmaxf((a0 + a1) + (a2 + a3), 0.0f);
            }
            // write w_b as bf16 [hi_b | lo_b] over the stage bytes just consumed
            char* wtp = smem + OFF_S + row * SW + 64*b;
            unsigned hp[8], lp[8];
            #pragma unroll
            for (int t = 0; t < 8; t++) split2(wv[2*t], wv[2*t+1], hp[t], lp[t]);
            *reinterpret_cast<uint4*>(wtp)      = make_uint4(hp[0], hp[1], hp[2], hp[3]);
            *reinterpret_cast<uint4*>(wtp + 16) = make_uint4(hp[4], hp[5], hp[6], hp[7]);
            *reinterpret_cast<uint4*>(wtp + 32) = make_uint4(lp[0], lp[1], lp[2], lp[3]);
            *reinterpret_cast<uint4*>(wtp + 48) = make_uint4(lp[4], lp[5], lp[6], lp[7]);
        }
        __syncwarp();

        // --- HMMA update of remaining cols, then spill next block to stage ---
        if (b < 3) {
            unsigned ahi[4], alo[4];
            ldsm4(ahi, a_wt + 64*b);
            ldsm4(alo, a_wt + 64*b + 32);
            #pragma unroll
            for (int p = 1; p < 4; p++) {
                if (p <= b) continue;             // compile-time trimmed
                unsigned bh[4], bl[4];
                const uint32_t bb = b_d11 + (p - 1) * 16 * SW;
                ldsm4(bh, bb + 32*b);
                ldsm4(bl, bb + 128 + 32*b);
                mma16816(acc[2*p    ], ahi, bh[0], bh[2]);
                mma16816(acc[2*p + 1], ahi, bh[1], bh[3]);
                mma16816(acc[2*p    ], alo, bh[0], bh[2]);
                mma16816(acc[2*p + 1], alo, bh[1], bh[3]);
                mma16816(acc[2*p    ], ahi, bl[0], bl[2]);
                mma16816(acc[2*p + 1], ahi, bl[1], bl[3]);
            }
            #pragma unroll
            for (int n = 2*(b+1); n <= 2*(b+1) + 1; n++) {
                const int c0 = 8*n + 2*q;
                *reinterpret_cast<float2*>(stage + (16*wid + rh    ) * 68 + c0) = make_float2(acc[n][0], acc[n][1]);
                *reinterpret_cast<float2*>(stage + (16*wid + rh + 8) * 68 + c0) = make_float2(acc[n][2], acc[n][3]);
            }
            __syncwarp();
        }
    }
    __syncwarp();

    // ===== GEMM2b: acc2 += [w] x B1^T =====
    {
        #pragma unroll
        for (int c = 0; c < 4; c++) {
            unsigned ah[4], al[4];
            ldsm4(ah, a_wt + 64*c);             // w hi chunk c (interleaved layout)
            gemm_b8(acc2, b_w2b, SW, c,     ah);
            gemm_b8(acc2, b_w2b, SW, 4 + c, ah);
            ldsm4(al, a_wt + 64*c + 32);        // w lo chunk c
            gemm_b8(acc2, b_w2b, SW, c,     al);
        }
        __syncwarp();   // all wt fragment loads done before stage overwrite
        #pragma unroll
        for (int n = 0; n < 8; n++) {
            const int c0 = 8*n + 2*q;
            const float2 bx2 = *reinterpret_cast<const float2*>(sbx + c0);
            *reinterpret_cast<float2*>(stage + (16*wid + rh    ) * 68 + c0) =
                make_float2(acc2[n][0] + bx2.x, acc2[n][1] + bx2.y);
            *reinterpret_cast<float2*>(stage + (16*wid + rh + 8) * 68 + c0) =
                make_float2(acc2[n][2] + bx2.x, acc2[n][3] + bx2.y);
        }
    }
    __syncwarp();

    // ---------- store own 16 rows ----------
    float4* gout4 = reinterpret_cast<float4*>(gout);
    #pragma unroll
    for (int i = 0; i < 8; i++) {
        const int idx = i * 32 + lane;
        const int row = 16*wid + (idx >> 4), c = idx & 15;
        if (rowbase + row < N)
            gout4[(size_t)(rowbase + row) * 16 + c] =
                *reinterpret_cast<float4*>(stage + row * 68 + 4*c);
    }
}

extern "C" void kernel_launch(void* const* d_in, const int* in_sizes, int n_in,
                              void* d_out, int out_size) {
    (void)n_in; (void)out_size;
    const float* x   = (const float*)d_in[0];
    const float* u   = (const float*)d_in[1];
    const float* A   = (const float*)d_in[2];
    const float* B1  = (const float*)d_in[3];
    const float* B2  = (const float*)d_in[4];
    const float* C1  = (const float*)d_in[5];
    const float* D11 = (const float*)d_in[6];
    const float* D12 = (const float*)d_in[7];
    const float* bv  = (const float*)d_in[8];
    const float* bx  = (const float*)d_in[9];
    float* out = (float*)d_out;

    const int N = in_sizes[0] / 64;                     // 262144
    const int grid = (N + MROWS - 1) / MROWS;           // 1024

    renl2_prep_kernel<<<8, 128>>>(A, B1, B2, C1, D11, D12);

    cudaFuncSetAttribute(renl2_hmma_kernel,
                         cudaFuncAttributeMaxDynamicSharedMemorySize,
                         SMEM_BYTES);
    renl2_hmma_kernel<<<grid, NTHREADS, SMEM_BYTES>>>(
        x, u, D11, bv, bx, out, N);
}